// round 1
// baseline (speedup 1.0000x reference)
#include <cuda_runtime.h>
#include <math.h>

// Problem dims (fixed by the dataset)
#define E_  768
#define H_  12
#define D_  64
#define B_  8
#define LO_ 512
#define LV_ 1024
#define LL_ 1024
#define LS_ 2048   // LV_ + LL_

// GEMM tiling
#define BM 128
#define BN 64
#define BK 16

// ---------------------------------------------------------------------------
// Scratch: __device__ globals (no allocation allowed anywhere).
// ---------------------------------------------------------------------------
__device__ float g_q1[(size_t)B_ * LO_ * E_];
__device__ float g_q2[(size_t)B_ * LO_ * E_];
__device__ float g_k1[(size_t)B_ * LV_ * E_];
__device__ float g_v1[(size_t)B_ * LV_ * E_];
__device__ float g_k2[(size_t)B_ * LL_ * E_];
__device__ float g_v2[(size_t)B_ * LL_ * E_];
__device__ float g_p [(size_t)B_ * H_ * LO_ * LS_];   // scores -> probs (in place)
__device__ float g_ctx[(size_t)B_ * LO_ * E_];

// ---------------------------------------------------------------------------
// Generic NT GEMM with bias:  C[m,n] = sum_k A[m,k] * W[n,k] + bias[n]
// A: (gridDim.y*BM) x K row-major (lda), W: (gridDim.x*BN) x K row-major (ldw)
// All dims assumed multiples of tile sizes (true for this problem).
// ---------------------------------------------------------------------------
__global__ __launch_bounds__(256) void gemm_nt_bias(
    const float* __restrict__ A, int lda,
    const float* __restrict__ W, int ldw,
    const float* __restrict__ bias,
    float* __restrict__ C, int ldc, int K)
{
    __shared__ float As[BK][BM];
    __shared__ float Ws[BK][BN];

    const int m0 = blockIdx.y * BM;
    const int n0 = blockIdx.x * BN;
    const int tid = threadIdx.x;
    const int tn = (tid & 15) * 4;   // 0..60
    const int tm = (tid >> 4) * 8;   // 0..120

    const float* Ab = A + (size_t)m0 * lda;
    const float* Wb = W + (size_t)n0 * ldw;

    float acc[8][4] = {};

    for (int k0 = 0; k0 < K; k0 += BK) {
        // A tile: 128x16 floats = 512 float4, 2 per thread
        #pragma unroll
        for (int i = 0; i < 2; i++) {
            int idx = tid + i * 256;
            int r = idx >> 2;
            int c = (idx & 3) * 4;
            float4 v = *(const float4*)(Ab + (size_t)r * lda + k0 + c);
            As[c + 0][r] = v.x; As[c + 1][r] = v.y;
            As[c + 2][r] = v.z; As[c + 3][r] = v.w;
        }
        // W tile: 64x16 floats = 256 float4, 1 per thread
        {
            int r = tid >> 2;
            int c = (tid & 3) * 4;
            float4 v = *(const float4*)(Wb + (size_t)r * ldw + k0 + c);
            Ws[c + 0][r] = v.x; Ws[c + 1][r] = v.y;
            Ws[c + 2][r] = v.z; Ws[c + 3][r] = v.w;
        }
        __syncthreads();
        #pragma unroll
        for (int k = 0; k < BK; k++) {
            float a[8], w[4];
            #pragma unroll
            for (int i = 0; i < 8; i++) a[i] = As[k][tm + i];
            #pragma unroll
            for (int j = 0; j < 4; j++) w[j] = Ws[k][tn + j];
            #pragma unroll
            for (int i = 0; i < 8; i++)
                #pragma unroll
                for (int j = 0; j < 4; j++)
                    acc[i][j] = fmaf(a[i], w[j], acc[i][j]);
        }
        __syncthreads();
    }

    float4 bv = *(const float4*)(bias + n0 + tn);
    #pragma unroll
    for (int i = 0; i < 8; i++) {
        int m = m0 + tm + i;
        float4 o;
        o.x = acc[i][0] + bv.x;
        o.y = acc[i][1] + bv.y;
        o.z = acc[i][2] + bv.z;
        o.w = acc[i][3] + bv.w;
        *(float4*)(C + (size_t)m * ldc + n0 + tn) = o;
    }
}

// ---------------------------------------------------------------------------
// Scores: S[b,h,t,s] = 0.125 * <Q?[b,t,h,:], K?[b,s',h,:]> + mask[t,s]
// s < 1024 -> (Q1,K1), else (Q2,K2) with s' = s-1024.
// Batched over z = b*H + h; M=512, N=2048, K=64.
// ---------------------------------------------------------------------------
__global__ __launch_bounds__(256) void scores_kernel(
    const float* __restrict__ Q1, const float* __restrict__ Q2,
    const float* __restrict__ K1c, const float* __restrict__ K2c,
    const float* __restrict__ mask, float* __restrict__ S)
{
    __shared__ float As[BK][BM];
    __shared__ float Ws[BK][BN];

    const int z = blockIdx.z;
    const int b = z / H_, h = z % H_;
    const int n0 = blockIdx.x * BN;   // 0..2047
    const int m0 = blockIdx.y * BM;   // 0..511
    const bool src2 = (n0 >= LV_);

    const float* A = (src2 ? Q2 : Q1) + ((size_t)b * LO_ + m0) * E_ + h * D_;
    const float* W = (src2 ? K2c : K1c)
                   + ((size_t)b * LV_ + (src2 ? n0 - LV_ : n0)) * E_ + h * D_;

    const int tid = threadIdx.x;
    const int tn = (tid & 15) * 4;
    const int tm = (tid >> 4) * 8;

    float acc[8][4] = {};

    for (int k0 = 0; k0 < D_; k0 += BK) {
        #pragma unroll
        for (int i = 0; i < 2; i++) {
            int idx = tid + i * 256;
            int r = idx >> 2;
            int c = (idx & 3) * 4;
            float4 v = *(const float4*)(A + (size_t)r * E_ + k0 + c);
            As[c + 0][r] = v.x; As[c + 1][r] = v.y;
            As[c + 2][r] = v.z; As[c + 3][r] = v.w;
        }
        {
            int r = tid >> 2;
            int c = (tid & 3) * 4;
            float4 v = *(const float4*)(W + (size_t)r * E_ + k0 + c);
            Ws[c + 0][r] = v.x; Ws[c + 1][r] = v.y;
            Ws[c + 2][r] = v.z; Ws[c + 3][r] = v.w;
        }
        __syncthreads();
        #pragma unroll
        for (int k = 0; k < BK; k++) {
            float a[8], w[4];
            #pragma unroll
            for (int i = 0; i < 8; i++) a[i] = As[k][tm + i];
            #pragma unroll
            for (int j = 0; j < 4; j++) w[j] = Ws[k][tn + j];
            #pragma unroll
            for (int i = 0; i < 8; i++)
                #pragma unroll
                for (int j = 0; j < 4; j++)
                    acc[i][j] = fmaf(a[i], w[j], acc[i][j]);
        }
        __syncthreads();
    }

    #pragma unroll
    for (int i = 0; i < 8; i++) {
        int m = m0 + tm + i;
        float4 mk = *(const float4*)(mask + (size_t)m * LS_ + n0 + tn);
        float4 o;
        o.x = acc[i][0] * 0.125f + mk.x;
        o.y = acc[i][1] * 0.125f + mk.y;
        o.z = acc[i][2] * 0.125f + mk.z;
        o.w = acc[i][3] * 0.125f + mk.w;
        *(float4*)(S + ((size_t)z * LO_ + m) * LS_ + n0 + tn) = o;
    }
}

// ---------------------------------------------------------------------------
// Softmax (in place over rows of length 2048) + head-average output.
// One block per (b, t). Loops over the 12 heads, accumulates avg in smem.
// ---------------------------------------------------------------------------
__global__ __launch_bounds__(256) void softmax_kernel(
    float* __restrict__ S, float* __restrict__ avg_out)
{
    __shared__ float row[LS_];
    __shared__ float avg[LS_];
    __shared__ float red[8];

    const int bt = blockIdx.x;
    const int b = bt / LO_, t = bt % LO_;
    const int tid = threadIdx.x;
    const int lane = tid & 31, wid = tid >> 5;

    for (int i = tid; i < LS_; i += 256) avg[i] = 0.f;

    for (int h = 0; h < H_; h++) {
        float* Srow = S + (((size_t)(b * H_ + h)) * LO_ + t) * LS_;

        // 1) load + max
        float lmax = -1e30f;
        for (int i = tid; i < LS_; i += 256) {
            float v = Srow[i];
            row[i] = v;
            lmax = fmaxf(lmax, v);
        }
        #pragma unroll
        for (int o = 16; o; o >>= 1) lmax = fmaxf(lmax, __shfl_xor_sync(~0u, lmax, o));
        if (lane == 0) red[wid] = lmax;
        __syncthreads();
        float m = red[0];
        #pragma unroll
        for (int i = 1; i < 8; i++) m = fmaxf(m, red[i]);

        // 2) exp + sum
        float lsum = 0.f;
        for (int i = tid; i < LS_; i += 256) {
            float e = __expf(row[i] - m);
            row[i] = e;
            lsum += e;
        }
        #pragma unroll
        for (int o = 16; o; o >>= 1) lsum += __shfl_xor_sync(~0u, lsum, o);
        __syncthreads();                 // protect red[] reuse
        if (lane == 0) red[wid] = lsum;
        __syncthreads();
        float ssum = red[0];
        #pragma unroll
        for (int i = 1; i < 8; i++) ssum += red[i];
        float inv = 1.f / ssum;

        // 3) normalize, write back, accumulate head-average
        for (int i = tid; i < LS_; i += 256) {
            float p = row[i] * inv;
            Srow[i] = p;
            avg[i] += p * (1.f / (float)H_);
        }
        __syncthreads();                 // row[]/red[] reuse next head
    }

    for (int i = tid; i < LS_; i += 256)
        avg_out[(size_t)bt * LS_ + i] = avg[i];
}

// ---------------------------------------------------------------------------
// Context: ctx[b,t,h*64+dd] = sum_s P[b,h,t,s] * Vcat[b,s,h,dd]
// NN GEMM, batched over z = b*H + h; M=512, N=64, K=2048. V source switches
// at k=1024 (V1 -> V2).
// ---------------------------------------------------------------------------
__global__ __launch_bounds__(256) void ctx_kernel(
    const float* __restrict__ P,
    const float* __restrict__ V1, const float* __restrict__ V2,
    float* __restrict__ CTX)
{
    __shared__ float As[BK][BM];
    __shared__ float Bs[BK][BN];

    const int z = blockIdx.z;
    const int b = z / H_, h = z % H_;
    const int m0 = blockIdx.y * BM;
    const float* A = P + ((size_t)z * LO_ + m0) * LS_;

    const int tid = threadIdx.x;
    const int tn = (tid & 15) * 4;
    const int tm = (tid >> 4) * 8;

    float acc[8][4] = {};

    for (int k0 = 0; k0 < LS_; k0 += BK) {
        #pragma unroll
        for (int i = 0; i < 2; i++) {
            int idx = tid + i * 256;
            int r = idx >> 2;
            int c = (idx & 3) * 4;
            float4 v = *(const float4*)(A + (size_t)r * LS_ + k0 + c);
            As[c + 0][r] = v.x; As[c + 1][r] = v.y;
            As[c + 2][r] = v.z; As[c + 3][r] = v.w;
        }
        {
            const float* Bsrc = (k0 < LV_)
                ? V1 + ((size_t)b * LV_ + k0) * E_ + h * D_
                : V2 + ((size_t)b * LL_ + (k0 - LV_)) * E_ + h * D_;
            int r = tid >> 4;          // 0..15 (k within tile)
            int c = (tid & 15) * 4;    // 0..60 (n)
            float4 v = *(const float4*)(Bsrc + (size_t)r * E_ + c);
            *(float4*)&Bs[r][c] = v;
        }
        __syncthreads();
        #pragma unroll
        for (int k = 0; k < BK; k++) {
            float a[8], w[4];
            #pragma unroll
            for (int i = 0; i < 8; i++) a[i] = As[k][tm + i];
            #pragma unroll
            for (int j = 0; j < 4; j++) w[j] = Bs[k][tn + j];
            #pragma unroll
            for (int i = 0; i < 8; i++)
                #pragma unroll
                for (int j = 0; j < 4; j++)
                    acc[i][j] = fmaf(a[i], w[j], acc[i][j]);
        }
        __syncthreads();
    }

    #pragma unroll
    for (int i = 0; i < 8; i++) {
        int m = m0 + tm + i;
        float4 o = make_float4(acc[i][0], acc[i][1], acc[i][2], acc[i][3]);
        *(float4*)(CTX + ((size_t)b * LO_ + m) * E_ + h * D_ + tn) = o;
    }
}

// ---------------------------------------------------------------------------
// Launch
// ---------------------------------------------------------------------------
extern "C" void kernel_launch(void* const* d_in, const int* in_sizes, int n_in,
                              void* d_out, int out_size)
{
    (void)in_sizes; (void)n_in; (void)out_size;

    const float* V    = (const float*)d_in[0];
    const float* L    = (const float*)d_in[1];
    const float* O    = (const float*)d_in[2];
    const float* mask = (const float*)d_in[3];
    const float* w1   = (const float*)d_in[4];
    const float* b1   = (const float*)d_in[5];
    const float* w2   = (const float*)d_in[6];
    const float* b2   = (const float*)d_in[7];
    const float* ow   = (const float*)d_in[8];
    const float* ob   = (const float*)d_in[9];

    float* out = (float*)d_out;                       // [B, LO, E]
    float* avg = out + (size_t)B_ * LO_ * E_;         // [B, LO, LS]

    float *q1, *q2, *k1, *v1, *k2, *v2, *p, *ctx;
    cudaGetSymbolAddress((void**)&q1,  g_q1);
    cudaGetSymbolAddress((void**)&q2,  g_q2);
    cudaGetSymbolAddress((void**)&k1,  g_k1);
    cudaGetSymbolAddress((void**)&v1,  g_v1);
    cudaGetSymbolAddress((void**)&k2,  g_k2);
    cudaGetSymbolAddress((void**)&v2,  g_v2);
    cudaGetSymbolAddress((void**)&p,   g_p);
    cudaGetSymbolAddress((void**)&ctx, g_ctx);

    dim3 blk(256);
    const size_t EE = (size_t)E_ * E_;

    // Projections (NT GEMMs with bias)
    dim3 gQ(E_ / BN, (B_ * LO_) / BM);   // 12 x 32
    dim3 gK(E_ / BN, (B_ * LV_) / BM);   // 12 x 64
    gemm_nt_bias<<<gQ, blk>>>(O, E_, w1,          E_, b1,          q1, E_, E_);
    gemm_nt_bias<<<gQ, blk>>>(O, E_, w2,          E_, b2,          q2, E_, E_);
    gemm_nt_bias<<<gK, blk>>>(V, E_, w1 + EE,     E_, b1 + E_,     k1, E_, E_);
    gemm_nt_bias<<<gK, blk>>>(V, E_, w1 + 2 * EE, E_, b1 + 2 * E_, v1, E_, E_);
    gemm_nt_bias<<<gK, blk>>>(L, E_, w2 + EE,     E_, b2 + E_,     k2, E_, E_);
    gemm_nt_bias<<<gK, blk>>>(L, E_, w2 + 2 * EE, E_, b2 + 2 * E_, v2, E_, E_);

    // Scores
    dim3 gS(LS_ / BN, LO_ / BM, B_ * H_);   // 32 x 4 x 96
    scores_kernel<<<gS, blk>>>(q1, q2, k1, k2, mask, p);

    // Softmax + head-average
    softmax_kernel<<<B_ * LO_, 256>>>(p, avg);

    // Context
    dim3 gC(1, LO_ / BM, B_ * H_);          // 1 x 4 x 96
    ctx_kernel<<<gC, blk>>>(p, v1, v2, ctx);

    // Output projection
    gemm_nt_bias<<<gQ, blk>>>(ctx, E_, ow, E_, ob, out, E_, E_);
}

// round 3
// speedup vs baseline: 1.4038x; 1.4038x over previous
#include <cuda_runtime.h>
#include <cuda_bf16.h>
#include <math.h>
#include <stdint.h>

// Problem dims
#define E_  768
#define H_  12
#define D_  64
#define B_  8
#define LO_ 512
#define LV_ 1024
#define LL_ 1024
#define LS_ 2048

// Split-K' GEMM config (bf16 hi/lo tripled K)
#define KP 2304          // 3 * 768
#define BKM 32           // K per mainloop iter (bf16)
#define NITER (KP / BKM) // 72

// fp32 GEMM tiling (attention kernels)
#define BM 128
#define BN 64
#define BK 16

// ---------------------------------------------------------------------------
// Scratch (__device__ globals; no allocation allowed)
// ---------------------------------------------------------------------------
__device__ float g_q1[(size_t)B_ * LO_ * E_];
__device__ float g_q2[(size_t)B_ * LO_ * E_];
__device__ float g_k1[(size_t)B_ * LV_ * E_];
__device__ float g_v1[(size_t)B_ * LV_ * E_];
__device__ float g_k2[(size_t)B_ * LL_ * E_];
__device__ float g_v2[(size_t)B_ * LL_ * E_];
__device__ float g_p [(size_t)B_ * H_ * LO_ * LS_];
__device__ float g_ctx[(size_t)B_ * LO_ * E_];

// bf16 split (K-tripled) operands
__device__ __nv_bfloat16 g_O3 [(size_t)B_ * LO_ * KP];
__device__ __nv_bfloat16 g_V3 [(size_t)B_ * LV_ * KP];
__device__ __nv_bfloat16 g_L3 [(size_t)B_ * LL_ * KP];
__device__ __nv_bfloat16 g_C3 [(size_t)B_ * LO_ * KP];
__device__ __nv_bfloat16 g_w13[(size_t)(3 * E_) * KP];
__device__ __nv_bfloat16 g_w23[(size_t)(3 * E_) * KP];
__device__ __nv_bfloat16 g_ow3[(size_t)E_ * KP];

// ---------------------------------------------------------------------------
// Helpers
// ---------------------------------------------------------------------------
__device__ __forceinline__ uint32_t smem_u32(const void* p) {
    uint32_t a;
    asm("{ .reg .u64 t; cvta.to.shared.u64 t, %1; cvt.u32.u64 %0, t; }"
        : "=r"(a) : "l"(p));
    return a;
}
__device__ __forceinline__ void cpa16(uint32_t s, const void* g) {
    asm volatile("cp.async.cg.shared.global [%0], [%1], 16;" :: "r"(s), "l"(g));
}
__device__ __forceinline__ void ldm_x4(uint32_t& r0, uint32_t& r1, uint32_t& r2,
                                       uint32_t& r3, uint32_t addr) {
    asm volatile("ldmatrix.sync.aligned.m8n8.x4.shared.b16 {%0,%1,%2,%3}, [%4];"
        : "=r"(r0), "=r"(r1), "=r"(r2), "=r"(r3) : "r"(addr));
}
__device__ __forceinline__ void mma16816(float* d, const uint32_t* a,
                                         uint32_t b0, uint32_t b1) {
    asm volatile(
        "mma.sync.aligned.m16n8k16.row.col.f32.bf16.bf16.f32 "
        "{%0,%1,%2,%3}, {%4,%5,%6,%7}, {%8,%9}, {%0,%1,%2,%3};"
        : "+f"(d[0]), "+f"(d[1]), "+f"(d[2]), "+f"(d[3])
        : "r"(a[0]), "r"(a[1]), "r"(a[2]), "r"(a[3]), "r"(b0), "r"(b1));
}

// ---------------------------------------------------------------------------
// Split-3 conversion: x[r,768] fp32 -> y[r,2304] bf16.
// mode 0 (activation): planes (hi, lo, hi);  mode 1 (weight): (hi, hi, lo)
// ---------------------------------------------------------------------------
__global__ __launch_bounds__(256) void split3_kernel(
    const float* __restrict__ x, __nv_bfloat16* __restrict__ y, int nrows, int wmode)
{
    int gid = blockIdx.x * 256 + threadIdx.x;
    int total = nrows * (E_ / 4);
    if (gid >= total) return;
    int r = gid / (E_ / 4);
    int c4 = (gid % (E_ / 4)) * 4;
    float4 v = *(const float4*)(x + (size_t)r * E_ + c4);
    float vv[4] = {v.x, v.y, v.z, v.w};
    uint64_t hp = 0, lp = 0;
    #pragma unroll
    for (int i = 0; i < 4; i++) {
        __nv_bfloat16 hi = __float2bfloat16(vv[i]);
        __nv_bfloat16 lo = __float2bfloat16(vv[i] - __bfloat162float(hi));
        hp |= (uint64_t)__bfloat16_as_ushort(hi) << (16 * i);
        lp |= (uint64_t)__bfloat16_as_ushort(lo) << (16 * i);
    }
    char* row = (char*)(y + (size_t)r * KP + c4);
    const int plane = E_ * 2;
    if (wmode) {
        *(uint64_t*)(row)             = hp;
        *(uint64_t*)(row + plane)     = hp;
        *(uint64_t*)(row + 2 * plane) = lp;
    } else {
        *(uint64_t*)(row)             = hp;
        *(uint64_t*)(row + plane)     = lp;
        *(uint64_t*)(row + 2 * plane) = hp;
    }
}

// ---------------------------------------------------------------------------
// HMMA GEMM (mma.sync bf16): C[m,n] = sum_k' A3[m,k']*W3[n,k'] + bias[n]
// CTA 128x128, BK=32, double-buffered cp.async, 8 warps of 64x32 tiles.
// ldc = 768 fixed. Grid: (N/128, M/128), 256 threads.
// ---------------------------------------------------------------------------
#define PADK 40                       // padded row stride (bf16 elems)
#define TILE_E (128 * PADK)           // elems per tile buffer

__global__ __launch_bounds__(256) void gemm_mma(
    const __nv_bfloat16* __restrict__ A3,
    const __nv_bfloat16* __restrict__ W3,
    const float* __restrict__ bias,
    float* __restrict__ C)
{
    __shared__ __align__(16) __nv_bfloat16 As[2][TILE_E];
    __shared__ __align__(16) __nv_bfloat16 Bs[2][TILE_E];

    const int tid  = threadIdx.x;
    const int warp = tid >> 5, lane = tid & 31;
    const int wm = warp >> 2, wn = warp & 3;     // warp grid 2(M) x 4(N)
    const int m0 = blockIdx.y * 128;
    const int n0 = blockIdx.x * 128;

    const uint32_t baseA = smem_u32(&As[0][0]);
    const uint32_t baseB = smem_u32(&Bs[0][0]);

    // cp.async slots: 512 chunks of 16B per tile; 2 per thread per tile.
    int r_ld[2], c_ld[2];
    #pragma unroll
    for (int i = 0; i < 2; i++) {
        int idx = tid + i * 256;
        r_ld[i] = idx >> 2;
        c_ld[i] = (idx & 3) * 8;     // bf16 elems (16B)
    }

    #define LOAD_STAGE(j, buf) do { \
        int _ko = (j) * BKM; \
        _Pragma("unroll") \
        for (int _i = 0; _i < 2; _i++) { \
            cpa16(baseA + 2u * ((buf) * TILE_E + r_ld[_i] * PADK + c_ld[_i]), \
                  A3 + (size_t)(m0 + r_ld[_i]) * KP + _ko + c_ld[_i]); \
            cpa16(baseB + 2u * ((buf) * TILE_E + r_ld[_i] * PADK + c_ld[_i]), \
                  W3 + (size_t)(n0 + r_ld[_i]) * KP + _ko + c_ld[_i]); \
        } \
        asm volatile("cp.async.commit_group;" ::: "memory"); \
    } while (0)

    LOAD_STAGE(0, 0);
    LOAD_STAGE(1, 1);

    // ldmatrix per-thread bases
    const int lr = lane & 15;          // row within 16-row tile
    const int lh = (lane >> 4) * 8;    // k-half offset (elems)

    float acc[4][4][4];
    #pragma unroll
    for (int i = 0; i < 4; i++)
        #pragma unroll
        for (int j = 0; j < 4; j++)
            #pragma unroll
            for (int q = 0; q < 4; q++) acc[i][j][q] = 0.f;

    for (int kt = 0; kt < NITER; kt++) {
        if (kt + 1 < NITER)
            asm volatile("cp.async.wait_group 1;" ::: "memory");
        else
            asm volatile("cp.async.wait_group 0;" ::: "memory");
        __syncthreads();

        const int buf = kt & 1;
        const uint32_t abase = baseA + 2u * (buf * TILE_E);
        const uint32_t bbase = baseB + 2u * (buf * TILE_E);

        #pragma unroll
        for (int kf = 0; kf < 2; kf++) {
            uint32_t a[4][4];
            #pragma unroll
            for (int mi = 0; mi < 4; mi++) {
                uint32_t ad = abase + 2u * ((wm * 64 + mi * 16 + lr) * PADK
                                            + kf * 16 + lh);
                ldm_x4(a[mi][0], a[mi][1], a[mi][2], a[mi][3], ad);
            }
            uint32_t br[2][4];
            #pragma unroll
            for (int g = 0; g < 2; g++) {
                uint32_t bd = bbase + 2u * ((wn * 32 + g * 16 + lr) * PADK
                                            + kf * 16 + lh);
                ldm_x4(br[g][0], br[g][1], br[g][2], br[g][3], bd);
            }
            #pragma unroll
            for (int mi = 0; mi < 4; mi++)
                #pragma unroll
                for (int g = 0; g < 2; g++)
                    #pragma unroll
                    for (int s = 0; s < 2; s++)
                        mma16816(acc[mi][g * 2 + s], a[mi], br[g][s], br[g][s + 2]);
        }
        __syncthreads();
        if (kt + 2 < NITER) LOAD_STAGE(kt + 2, buf);
    }
    #undef LOAD_STAGE

    // Epilogue: acc layout per mma tile: lane -> (row = lane/4 (+8), col = 2*(lane%4))
    const int er = lane >> 2;
    const int ec = (lane & 3) * 2;
    #pragma unroll
    for (int mi = 0; mi < 4; mi++) {
        #pragma unroll
        for (int ni = 0; ni < 4; ni++) {
            int m = m0 + wm * 64 + mi * 16 + er;
            int n = n0 + wn * 32 + ni * 8 + ec;
            float bx = __ldg(bias + n), by = __ldg(bias + n + 1);
            float2 o0 = make_float2(acc[mi][ni][0] + bx, acc[mi][ni][1] + by);
            float2 o1 = make_float2(acc[mi][ni][2] + bx, acc[mi][ni][3] + by);
            *(float2*)(C + (size_t)m * E_ + n)       = o0;
            *(float2*)(C + (size_t)(m + 8) * E_ + n) = o1;
        }
    }
}

// ---------------------------------------------------------------------------
// Scores (fp32): S[b,h,t,s] = 0.125 * <Q,K> + mask[t,s]
// ---------------------------------------------------------------------------
__global__ __launch_bounds__(256) void scores_kernel(
    const float* __restrict__ Q1, const float* __restrict__ Q2,
    const float* __restrict__ K1c, const float* __restrict__ K2c,
    const float* __restrict__ mask, float* __restrict__ S)
{
    __shared__ float As[BK][BM];
    __shared__ float Ws[BK][BN];

    const int z = blockIdx.z;
    const int b = z / H_, h = z % H_;
    const int n0 = blockIdx.x * BN;
    const int m0 = blockIdx.y * BM;
    const bool src2 = (n0 >= LV_);

    const float* A = (src2 ? Q2 : Q1) + ((size_t)b * LO_ + m0) * E_ + h * D_;
    const float* W = (src2 ? K2c : K1c)
                   + ((size_t)b * LV_ + (src2 ? n0 - LV_ : n0)) * E_ + h * D_;

    const int tid = threadIdx.x;
    const int tn = (tid & 15) * 4;
    const int tm = (tid >> 4) * 8;

    float acc[8][4] = {};

    for (int k0 = 0; k0 < D_; k0 += BK) {
        #pragma unroll
        for (int i = 0; i < 2; i++) {
            int idx = tid + i * 256;
            int r = idx >> 2;
            int c = (idx & 3) * 4;
            float4 v = *(const float4*)(A + (size_t)r * E_ + k0 + c);
            As[c + 0][r] = v.x; As[c + 1][r] = v.y;
            As[c + 2][r] = v.z; As[c + 3][r] = v.w;
        }
        {
            int r = tid >> 2;
            int c = (tid & 3) * 4;
            float4 v = *(const float4*)(W + (size_t)r * E_ + k0 + c);
            Ws[c + 0][r] = v.x; Ws[c + 1][r] = v.y;
            Ws[c + 2][r] = v.z; Ws[c + 3][r] = v.w;
        }
        __syncthreads();
        #pragma unroll
        for (int k = 0; k < BK; k++) {
            float a[8], w[4];
            #pragma unroll
            for (int i = 0; i < 8; i++) a[i] = As[k][tm + i];
            #pragma unroll
            for (int j = 0; j < 4; j++) w[j] = Ws[k][tn + j];
            #pragma unroll
            for (int i = 0; i < 8; i++)
                #pragma unroll
                for (int j = 0; j < 4; j++)
                    acc[i][j] = fmaf(a[i], w[j], acc[i][j]);
        }
        __syncthreads();
    }

    #pragma unroll
    for (int i = 0; i < 8; i++) {
        int m = m0 + tm + i;
        float4 mk = *(const float4*)(mask + (size_t)m * LS_ + n0 + tn);
        float4 o;
        o.x = acc[i][0] * 0.125f + mk.x;
        o.y = acc[i][1] * 0.125f + mk.y;
        o.z = acc[i][2] * 0.125f + mk.z;
        o.w = acc[i][3] * 0.125f + mk.w;
        *(float4*)(S + ((size_t)z * LO_ + m) * LS_ + n0 + tn) = o;
    }
}

// ---------------------------------------------------------------------------
// Softmax + head-average
// ---------------------------------------------------------------------------
__global__ __launch_bounds__(256) void softmax_kernel(
    float* __restrict__ S, float* __restrict__ avg_out)
{
    __shared__ float row[LS_];
    __shared__ float avg[LS_];
    __shared__ float red[8];

    const int bt = blockIdx.x;
    const int b = bt / LO_, t = bt % LO_;
    const int tid = threadIdx.x;
    const int lane = tid & 31, wid = tid >> 5;

    for (int i = tid; i < LS_; i += 256) avg[i] = 0.f;

    for (int h = 0; h < H_; h++) {
        float* Srow = S + (((size_t)(b * H_ + h)) * LO_ + t) * LS_;

        float lmax = -1e30f;
        for (int i = tid; i < LS_; i += 256) {
            float v = Srow[i];
            row[i] = v;
            lmax = fmaxf(lmax, v);
        }
        #pragma unroll
        for (int o = 16; o; o >>= 1) lmax = fmaxf(lmax, __shfl_xor_sync(~0u, lmax, o));
        if (lane == 0) red[wid] = lmax;
        __syncthreads();
        float m = red[0];
        #pragma unroll
        for (int i = 1; i < 8; i++) m = fmaxf(m, red[i]);

        float lsum = 0.f;
        for (int i = tid; i < LS_; i += 256) {
            float e = __expf(row[i] - m);
            row[i] = e;
            lsum += e;
        }
        #pragma unroll
        for (int o = 16; o; o >>= 1) lsum += __shfl_xor_sync(~0u, lsum, o);
        __syncthreads();
        if (lane == 0) red[wid] = lsum;
        __syncthreads();
        float ssum = red[0];
        #pragma unroll
        for (int i = 1; i < 8; i++) ssum += red[i];
        float inv = 1.f / ssum;

        for (int i = tid; i < LS_; i += 256) {
            float p = row[i] * inv;
            Srow[i] = p;
            avg[i] += p * (1.f / (float)H_);
        }
        __syncthreads();
    }

    for (int i = tid; i < LS_; i += 256)
        avg_out[(size_t)bt * LS_ + i] = avg[i];
}

// ---------------------------------------------------------------------------
// Context (fp32)
// ---------------------------------------------------------------------------
__global__ __launch_bounds__(256) void ctx_kernel(
    const float* __restrict__ P,
    const float* __restrict__ V1, const float* __restrict__ V2,
    float* __restrict__ CTX)
{
    __shared__ float As[BK][BM];
    __shared__ float Bs[BK][BN];

    const int z = blockIdx.z;
    const int b = z / H_, h = z % H_;
    const int m0 = blockIdx.y * BM;
    const float* A = P + ((size_t)z * LO_ + m0) * LS_;

    const int tid = threadIdx.x;
    const int tn = (tid & 15) * 4;
    const int tm = (tid >> 4) * 8;

    float acc[8][4] = {};

    for (int k0 = 0; k0 < LS_; k0 += BK) {
        #pragma unroll
        for (int i = 0; i < 2; i++) {
            int idx = tid + i * 256;
            int r = idx >> 2;
            int c = (idx & 3) * 4;
            float4 v = *(const float4*)(A + (size_t)r * LS_ + k0 + c);
            As[c + 0][r] = v.x; As[c + 1][r] = v.y;
            As[c + 2][r] = v.z; As[c + 3][r] = v.w;
        }
        {
            const float* Bsrc = (k0 < LV_)
                ? V1 + ((size_t)b * LV_ + k0) * E_ + h * D_
                : V2 + ((size_t)b * LL_ + (k0 - LV_)) * E_ + h * D_;
            int r = tid >> 4;
            int c = (tid & 15) * 4;
            float4 v = *(const float4*)(Bsrc + (size_t)r * E_ + c);
            *(float4*)&Bs[r][c] = v;
        }
        __syncthreads();
        #pragma unroll
        for (int k = 0; k < BK; k++) {
            float a[8], w[4];
            #pragma unroll
            for (int i = 0; i < 8; i++) a[i] = As[k][tm + i];
            #pragma unroll
            for (int j = 0; j < 4; j++) w[j] = Bs[k][tn + j];
            #pragma unroll
            for (int i = 0; i < 8; i++)
                #pragma unroll
                for (int j = 0; j < 4; j++)
                    acc[i][j] = fmaf(a[i], w[j], acc[i][j]);
        }
        __syncthreads();
    }

    #pragma unroll
    for (int i = 0; i < 8; i++) {
        int m = m0 + tm + i;
        float4 o = make_float4(acc[i][0], acc[i][1], acc[i][2], acc[i][3]);
        *(float4*)(CTX + ((size_t)b * LO_ + m) * E_ + h * D_ + tn) = o;
    }
}

// ---------------------------------------------------------------------------
// Launch
// ---------------------------------------------------------------------------
extern "C" void kernel_launch(void* const* d_in, const int* in_sizes, int n_in,
                              void* d_out, int out_size)
{
    (void)in_sizes; (void)n_in; (void)out_size;

    const float* V    = (const float*)d_in[0];
    const float* L    = (const float*)d_in[1];
    const float* O    = (const float*)d_in[2];
    const float* mask = (const float*)d_in[3];
    const float* w1   = (const float*)d_in[4];
    const float* b1   = (const float*)d_in[5];
    const float* w2   = (const float*)d_in[6];
    const float* b2   = (const float*)d_in[7];
    const float* ow   = (const float*)d_in[8];
    const float* ob   = (const float*)d_in[9];

    float* out = (float*)d_out;
    float* avg = out + (size_t)B_ * LO_ * E_;

    float *q1, *q2, *k1, *v1, *k2, *v2, *p, *ctx;
    cudaGetSymbolAddress((void**)&q1,  g_q1);
    cudaGetSymbolAddress((void**)&q2,  g_q2);
    cudaGetSymbolAddress((void**)&k1,  g_k1);
    cudaGetSymbolAddress((void**)&v1,  g_v1);
    cudaGetSymbolAddress((void**)&k2,  g_k2);
    cudaGetSymbolAddress((void**)&v2,  g_v2);
    cudaGetSymbolAddress((void**)&p,   g_p);
    cudaGetSymbolAddress((void**)&ctx, g_ctx);

    __nv_bfloat16 *O3, *V3, *L3, *C3, *w13, *w23, *ow3;
    cudaGetSymbolAddress((void**)&O3,  g_O3);
    cudaGetSymbolAddress((void**)&V3,  g_V3);
    cudaGetSymbolAddress((void**)&L3,  g_L3);
    cudaGetSymbolAddress((void**)&C3,  g_C3);
    cudaGetSymbolAddress((void**)&w13, g_w13);
    cudaGetSymbolAddress((void**)&w23, g_w23);
    cudaGetSymbolAddress((void**)&ow3, g_ow3);

    dim3 blk(256);

    // 1) Split conversions
    auto cgrid = [](int rows) { return (rows * (E_ / 4) + 255) / 256; };
    split3_kernel<<<cgrid(B_ * LV_), 256>>>(V,  V3,  B_ * LV_, 0);
    split3_kernel<<<cgrid(B_ * LL_), 256>>>(L,  L3,  B_ * LL_, 0);
    split3_kernel<<<cgrid(B_ * LO_), 256>>>(O,  O3,  B_ * LO_, 0);
    split3_kernel<<<cgrid(3 * E_),   256>>>(w1, w13, 3 * E_,   1);
    split3_kernel<<<cgrid(3 * E_),   256>>>(w2, w23, 3 * E_,   1);
    split3_kernel<<<cgrid(E_),       256>>>(ow, ow3, E_,       1);

    // 2) Projections (HMMA bf16-split GEMMs)
    dim3 gQ(E_ / 128, (B_ * LO_) / 128);  // 6 x 32
    dim3 gK(E_ / 128, (B_ * LV_) / 128);  // 6 x 64
    const size_t WROW = (size_t)E_ * KP;
    gemm_mma<<<gQ, blk>>>(O3, w13,            b1,          q1);
    gemm_mma<<<gQ, blk>>>(O3, w23,            b2,          q2);
    gemm_mma<<<gK, blk>>>(V3, w13 + WROW,     b1 + E_,     k1);
    gemm_mma<<<gK, blk>>>(V3, w13 + 2 * WROW, b1 + 2 * E_, v1);
    gemm_mma<<<gK, blk>>>(L3, w23 + WROW,     b2 + E_,     k2);
    gemm_mma<<<gK, blk>>>(L3, w23 + 2 * WROW, b2 + 2 * E_, v2);

    // 3) Scores
    dim3 gS(LS_ / BN, LO_ / BM, B_ * H_);
    scores_kernel<<<gS, blk>>>(q1, q2, k1, k2, mask, p);

    // 4) Softmax + head-average
    softmax_kernel<<<B_ * LO_, 256>>>(p, avg);

    // 5) Context
    dim3 gC(1, LO_ / BM, B_ * H_);
    ctx_kernel<<<gC, blk>>>(p, v1, v2, ctx);

    // 6) Output projection
    split3_kernel<<<cgrid(B_ * LO_), 256>>>(ctx, C3, B_ * LO_, 0);
    gemm_mma<<<gQ, blk>>>(C3, ow3, ob, out);
}

// round 4
// speedup vs baseline: 1.7224x; 1.2270x over previous
#include <cuda_runtime.h>
#include <cuda_bf16.h>
#include <math.h>
#include <stdint.h>

// Problem dims
#define E_  768
#define H_  12
#define D_  64
#define B_  8
#define LO_ 512
#define LV_ 1024
#define LL_ 1024
#define LS_ 2048
#define Z_  (B_ * H_)     // 96

#define BKM 32            // bf16 K per mainloop chunk
#define PADK 40           // padded A/W row stride (elems)
#define PADB 72           // padded ctx-B row stride (elems)
#define TILE_AE (128 * PADK)              // elems per 128-row tile
#define STG_PROJ_B (2 * TILE_AE * 2)      // bytes per stage (A+B), proj/scores = 20480
#define STG_CTX_B (TILE_AE * 2 + 32 * PADB * 2)  // 10240 + 4608 = 14848
#define SMEM_PROJ (4 * STG_PROJ_B)        // 81920
#define SMEM_CTX  (4 * STG_CTX_B)         // 59392
#define RS2 (2 * E_)      // 1536: row stride of 2-plane [row][2][768] arrays

// ---------------------------------------------------------------------------
// Scratch
// ---------------------------------------------------------------------------
__device__ float g_S[(size_t)Z_ * LO_ * LS_];                   // scores fp32
__device__ __nv_bfloat16 g_Psp [(size_t)Z_ * LO_ * 2 * LS_];    // probs hi/lo
__device__ __nv_bfloat16 g_Osp [(size_t)B_ * LO_ * RS2];
__device__ __nv_bfloat16 g_Vsp [(size_t)B_ * LV_ * RS2];
__device__ __nv_bfloat16 g_Lsp [(size_t)B_ * LL_ * RS2];
__device__ __nv_bfloat16 g_q1sp[(size_t)B_ * LO_ * RS2];
__device__ __nv_bfloat16 g_q2sp[(size_t)B_ * LO_ * RS2];
__device__ __nv_bfloat16 g_k1sp[(size_t)B_ * LV_ * RS2];
__device__ __nv_bfloat16 g_v1sp[(size_t)B_ * LV_ * RS2];
__device__ __nv_bfloat16 g_k2sp[(size_t)B_ * LL_ * RS2];
__device__ __nv_bfloat16 g_v2sp[(size_t)B_ * LL_ * RS2];
__device__ __nv_bfloat16 g_ctxsp[(size_t)B_ * LO_ * RS2];
__device__ __nv_bfloat16 g_w1sp[(size_t)(3 * E_) * RS2];
__device__ __nv_bfloat16 g_w2sp[(size_t)(3 * E_) * RS2];
__device__ __nv_bfloat16 g_owsp[(size_t)E_ * RS2];

// ---------------------------------------------------------------------------
// Helpers
// ---------------------------------------------------------------------------
__device__ __forceinline__ uint32_t smem_u32(const void* p) {
    uint32_t a;
    asm("{ .reg .u64 t; cvta.to.shared.u64 t, %1; cvt.u32.u64 %0, t; }"
        : "=r"(a) : "l"(p));
    return a;
}
__device__ __forceinline__ void cpa16(uint32_t s, const void* g) {
    asm volatile("cp.async.cg.shared.global [%0], [%1], 16;" :: "r"(s), "l"(g));
}
__device__ __forceinline__ void ldm_x4(uint32_t& r0, uint32_t& r1, uint32_t& r2,
                                       uint32_t& r3, uint32_t addr) {
    asm volatile("ldmatrix.sync.aligned.m8n8.x4.shared.b16 {%0,%1,%2,%3}, [%4];"
        : "=r"(r0), "=r"(r1), "=r"(r2), "=r"(r3) : "r"(addr));
}
__device__ __forceinline__ void ldm_x4_t(uint32_t& r0, uint32_t& r1, uint32_t& r2,
                                         uint32_t& r3, uint32_t addr) {
    asm volatile("ldmatrix.sync.aligned.m8n8.x4.trans.shared.b16 {%0,%1,%2,%3}, [%4];"
        : "=r"(r0), "=r"(r1), "=r"(r2), "=r"(r3) : "r"(addr));
}
__device__ __forceinline__ void mma16816(float* d, const uint32_t* a,
                                         uint32_t b0, uint32_t b1) {
    asm volatile(
        "mma.sync.aligned.m16n8k16.row.col.f32.bf16.bf16.f32 "
        "{%0,%1,%2,%3}, {%4,%5,%6,%7}, {%8,%9}, {%0,%1,%2,%3};"
        : "+f"(d[0]), "+f"(d[1]), "+f"(d[2]), "+f"(d[3])
        : "r"(a[0]), "r"(a[1]), "r"(a[2]), "r"(a[3]), "r"(b0), "r"(b1));
}
__device__ __forceinline__ void fsplit(float x, __nv_bfloat16& h, __nv_bfloat16& l) {
    h = __float2bfloat16(x);
    l = __float2bfloat16(x - __bfloat162float(h));
}

// ---------------------------------------------------------------------------
// Split-2: x[r,768] fp32 -> y[r,2,768] bf16 (hi plane, lo plane)
// ---------------------------------------------------------------------------
__global__ __launch_bounds__(256) void split2_kernel(
    const float* __restrict__ x, __nv_bfloat16* __restrict__ y, int nrows)
{
    int gid = blockIdx.x * 256 + threadIdx.x;
    int total = nrows * (E_ / 4);
    if (gid >= total) return;
    int r = gid / (E_ / 4);
    int c4 = (gid % (E_ / 4)) * 4;
    float4 v = *(const float4*)(x + (size_t)r * E_ + c4);
    float vv[4] = {v.x, v.y, v.z, v.w};
    uint64_t hp = 0, lp = 0;
    #pragma unroll
    for (int i = 0; i < 4; i++) {
        __nv_bfloat16 hi, lo;
        fsplit(vv[i], hi, lo);
        hp |= (uint64_t)__bfloat16_as_ushort(hi) << (16 * i);
        lp |= (uint64_t)__bfloat16_as_ushort(lo) << (16 * i);
    }
    __nv_bfloat16* row = y + (size_t)r * RS2 + c4;
    *(uint64_t*)(row)      = hp;
    *(uint64_t*)(row + E_) = lp;
}

// ---------------------------------------------------------------------------
// Projection GEMM: C[m,n] = sum_k A[m,k]*W[n,k] + bias[n]
// A,W: 2-plane bf16 [rows][2][768]. K' = 3*768 = 2304, 72 chunks of 32,
// plane map per term: A(0,1,0), W(0,0,1). 4-stage cp.async, TMEM-free HMMA.
// split_out=1 -> write Cs as 2-plane bf16; else Cf fp32 (ldc=768).
// ---------------------------------------------------------------------------
__global__ __launch_bounds__(256) void gemm_proj(
    const __nv_bfloat16* __restrict__ A,
    const __nv_bfloat16* __restrict__ W,
    const float* __restrict__ bias,
    float* __restrict__ Cf,
    __nv_bfloat16* __restrict__ Cs,
    int split_out)
{
    extern __shared__ char smx[];
    const uint32_t base = smem_u32(smx);

    const int tid  = threadIdx.x;
    const int warp = tid >> 5, lane = tid & 31;
    const int wm = warp >> 2, wn = warp & 3;
    const int m0 = blockIdx.y * 128;
    const int n0 = blockIdx.x * 128;

    // load slots: 512 16B-chunks per tile, 2 per thread
    const __nv_bfloat16* aRow[2];
    const __nv_bfloat16* wRow[2];
    uint32_t offS[2];
    #pragma unroll
    for (int i = 0; i < 2; i++) {
        int idx = tid + i * 256;
        int r = idx >> 2, c8 = (idx & 3) * 8;
        aRow[i] = A + (size_t)(m0 + r) * RS2 + c8;
        wRow[i] = W + (size_t)(n0 + r) * RS2 + c8;
        offS[i] = 2u * (r * PADK + c8);
    }

    #define PLOAD(j) do { \
        int _t = (j) / 24, _ko = ((j) % 24) * 32; \
        int _ap = (_t == 1) ? E_ : 0, _wp = (_t == 2) ? E_ : 0; \
        uint32_t _sb = base + ((j) & 3) * STG_PROJ_B; \
        _Pragma("unroll") \
        for (int _i = 0; _i < 2; _i++) { \
            cpa16(_sb + offS[_i], aRow[_i] + _ap + _ko); \
            cpa16(_sb + 2 * TILE_AE + offS[_i], wRow[_i] + _wp + _ko); \
        } \
        asm volatile("cp.async.commit_group;" ::: "memory"); \
    } while (0)

    PLOAD(0); PLOAD(1); PLOAD(2);

    const int lr = lane & 15;
    const int lh = (lane >> 4) * 8;

    float acc[4][4][4];
    #pragma unroll
    for (int i = 0; i < 4; i++)
        #pragma unroll
        for (int j = 0; j < 4; j++)
            #pragma unroll
            for (int q = 0; q < 4; q++) acc[i][j][q] = 0.f;

    const int NCHUNK = 72;
    for (int c = 0; c < NCHUNK; c++) {
        asm volatile("cp.async.wait_group 2;" ::: "memory");
        __syncthreads();
        if (c + 3 < NCHUNK) PLOAD(c + 3);
        else asm volatile("cp.async.commit_group;" ::: "memory");

        const uint32_t ab = base + (c & 3) * STG_PROJ_B;
        const uint32_t bb = ab + 2 * TILE_AE;
        #pragma unroll
        for (int kf = 0; kf < 2; kf++) {
            uint32_t a[4][4];
            #pragma unroll
            for (int mi = 0; mi < 4; mi++)
                ldm_x4(a[mi][0], a[mi][1], a[mi][2], a[mi][3],
                       ab + 2u * ((wm * 64 + mi * 16 + lr) * PADK + kf * 16 + lh));
            uint32_t br[2][4];
            #pragma unroll
            for (int g = 0; g < 2; g++)
                ldm_x4(br[g][0], br[g][1], br[g][2], br[g][3],
                       bb + 2u * ((wn * 32 + g * 16 + lr) * PADK + kf * 16 + lh));
            #pragma unroll
            for (int mi = 0; mi < 4; mi++)
                #pragma unroll
                for (int g = 0; g < 2; g++)
                    #pragma unroll
                    for (int s = 0; s < 2; s++)
                        mma16816(acc[mi][g * 2 + s], a[mi], br[g][s], br[g][s + 2]);
        }
    }
    #undef PLOAD

    const int er = lane >> 2;
    const int ec = (lane & 3) * 2;
    #pragma unroll
    for (int mi = 0; mi < 4; mi++) {
        #pragma unroll
        for (int ni = 0; ni < 4; ni++) {
            int m = m0 + wm * 64 + mi * 16 + er;
            int n = n0 + wn * 32 + ni * 8 + ec;
            float bx = __ldg(bias + n), by = __ldg(bias + n + 1);
            float v00 = acc[mi][ni][0] + bx, v01 = acc[mi][ni][1] + by;
            float v10 = acc[mi][ni][2] + bx, v11 = acc[mi][ni][3] + by;
            if (split_out) {
                __nv_bfloat16 h0, l0, h1, l1;
                fsplit(v00, h0, l0); fsplit(v01, h1, l1);
                *(__nv_bfloat162*)(Cs + (size_t)m * RS2 + n)      = __nv_bfloat162(h0, h1);
                *(__nv_bfloat162*)(Cs + (size_t)m * RS2 + E_ + n) = __nv_bfloat162(l0, l1);
                fsplit(v10, h0, l0); fsplit(v11, h1, l1);
                *(__nv_bfloat162*)(Cs + (size_t)(m + 8) * RS2 + n)      = __nv_bfloat162(h0, h1);
                *(__nv_bfloat162*)(Cs + (size_t)(m + 8) * RS2 + E_ + n) = __nv_bfloat162(l0, l1);
            } else {
                *(float2*)(Cf + (size_t)m * E_ + n)       = make_float2(v00, v01);
                *(float2*)(Cf + (size_t)(m + 8) * E_ + n) = make_float2(v10, v11);
            }
        }
    }
}

// ---------------------------------------------------------------------------
// Scores HMMA: S[z,t,s] = 0.125 * <q[t,:], k[s,:]> + mask[t,s]
// Per head: K0=64, K'=192 -> 6 chunks. grid (16, 4, 96).
// ---------------------------------------------------------------------------
__global__ __launch_bounds__(256) void scores_mma(
    const __nv_bfloat16* __restrict__ Q1, const __nv_bfloat16* __restrict__ Q2,
    const __nv_bfloat16* __restrict__ K1, const __nv_bfloat16* __restrict__ K2,
    const float* __restrict__ mask, float* __restrict__ S)
{
    extern __shared__ char smx[];
    const uint32_t base = smem_u32(smx);

    const int tid  = threadIdx.x;
    const int warp = tid >> 5, lane = tid & 31;
    const int wm = warp >> 2, wn = warp & 3;
    const int z = blockIdx.z;
    const int b = z / H_, h = z % H_;
    const int m0 = blockIdx.y * 128;
    const int n0 = blockIdx.x * 128;
    const bool src2 = (n0 >= LV_);
    const int sr0 = src2 ? n0 - LV_ : n0;

    const __nv_bfloat16* Qb = (src2 ? Q2 : Q1);
    const __nv_bfloat16* Kb = (src2 ? K2 : K1);

    const __nv_bfloat16* aRow[2];
    const __nv_bfloat16* wRow[2];
    uint32_t offS[2];
    #pragma unroll
    for (int i = 0; i < 2; i++) {
        int idx = tid + i * 256;
        int r = idx >> 2, c8 = (idx & 3) * 8;
        aRow[i] = Qb + (size_t)(b * LO_ + m0 + r) * RS2 + h * D_ + c8;
        wRow[i] = Kb + (size_t)(b * LV_ + sr0 + r) * RS2 + h * D_ + c8;
        offS[i] = 2u * (r * PADK + c8);
    }

    #define SLOAD(j) do { \
        int _t = (j) >> 1, _ko = ((j) & 1) * 32; \
        int _ap = (_t == 1) ? E_ : 0, _wp = (_t == 2) ? E_ : 0; \
        uint32_t _sb = base + ((j) & 3) * STG_PROJ_B; \
        _Pragma("unroll") \
        for (int _i = 0; _i < 2; _i++) { \
            cpa16(_sb + offS[_i], aRow[_i] + _ap + _ko); \
            cpa16(_sb + 2 * TILE_AE + offS[_i], wRow[_i] + _wp + _ko); \
        } \
        asm volatile("cp.async.commit_group;" ::: "memory"); \
    } while (0)

    SLOAD(0); SLOAD(1); SLOAD(2);

    const int lr = lane & 15;
    const int lh = (lane >> 4) * 8;

    float acc[4][4][4];
    #pragma unroll
    for (int i = 0; i < 4; i++)
        #pragma unroll
        for (int j = 0; j < 4; j++)
            #pragma unroll
            for (int q = 0; q < 4; q++) acc[i][j][q] = 0.f;

    const int NCHUNK = 6;
    for (int c = 0; c < NCHUNK; c++) {
        asm volatile("cp.async.wait_group 2;" ::: "memory");
        __syncthreads();
        if (c + 3 < NCHUNK) SLOAD(c + 3);
        else asm volatile("cp.async.commit_group;" ::: "memory");

        const uint32_t ab = base + (c & 3) * STG_PROJ_B;
        const uint32_t bb = ab + 2 * TILE_AE;
        #pragma unroll
        for (int kf = 0; kf < 2; kf++) {
            uint32_t a[4][4];
            #pragma unroll
            for (int mi = 0; mi < 4; mi++)
                ldm_x4(a[mi][0], a[mi][1], a[mi][2], a[mi][3],
                       ab + 2u * ((wm * 64 + mi * 16 + lr) * PADK + kf * 16 + lh));
            uint32_t br[2][4];
            #pragma unroll
            for (int g = 0; g < 2; g++)
                ldm_x4(br[g][0], br[g][1], br[g][2], br[g][3],
                       bb + 2u * ((wn * 32 + g * 16 + lr) * PADK + kf * 16 + lh));
            #pragma unroll
            for (int mi = 0; mi < 4; mi++)
                #pragma unroll
                for (int g = 0; g < 2; g++)
                    #pragma unroll
                    for (int s = 0; s < 2; s++)
                        mma16816(acc[mi][g * 2 + s], a[mi], br[g][s], br[g][s + 2]);
        }
    }
    #undef SLOAD

    const int er = lane >> 2;
    const int ec = (lane & 3) * 2;
    #pragma unroll
    for (int mi = 0; mi < 4; mi++) {
        #pragma unroll
        for (int ni = 0; ni < 4; ni++) {
            int m = m0 + wm * 64 + mi * 16 + er;
            int n = n0 + wn * 32 + ni * 8 + ec;
            float2 mk0 = *(const float2*)(mask + (size_t)m * LS_ + n);
            float2 mk1 = *(const float2*)(mask + (size_t)(m + 8) * LS_ + n);
            float* d0 = S + ((size_t)z * LO_ + m) * LS_ + n;
            float* d1 = S + ((size_t)z * LO_ + m + 8) * LS_ + n;
            *(float2*)d0 = make_float2(acc[mi][ni][0] * 0.125f + mk0.x,
                                       acc[mi][ni][1] * 0.125f + mk0.y);
            *(float2*)d1 = make_float2(acc[mi][ni][2] * 0.125f + mk1.x,
                                       acc[mi][ni][3] * 0.125f + mk1.y);
        }
    }
}

// ---------------------------------------------------------------------------
// Softmax: reads S fp32, writes p as bf16 hi/lo planes + head-average.
// ---------------------------------------------------------------------------
__global__ __launch_bounds__(256) void softmax_kernel(
    const float* __restrict__ S, __nv_bfloat16* __restrict__ Psp,
    float* __restrict__ avg_out)
{
    __shared__ float row[LS_];
    __shared__ float avg[LS_];
    __shared__ float red[8];

    const int bt = blockIdx.x;
    const int b = bt / LO_, t = bt % LO_;
    const int tid = threadIdx.x;
    const int lane = tid & 31, wid = tid >> 5;

    for (int i = tid; i < LS_; i += 256) avg[i] = 0.f;

    for (int h = 0; h < H_; h++) {
        const float* Srow = S + (((size_t)(b * H_ + h)) * LO_ + t) * LS_;
        __nv_bfloat16* Prow = Psp + (((size_t)(b * H_ + h)) * LO_ + t) * (2 * LS_);

        float lmax = -1e30f;
        for (int i = tid; i < LS_; i += 256) {
            float v = Srow[i];
            row[i] = v;
            lmax = fmaxf(lmax, v);
        }
        #pragma unroll
        for (int o = 16; o; o >>= 1) lmax = fmaxf(lmax, __shfl_xor_sync(~0u, lmax, o));
        if (lane == 0) red[wid] = lmax;
        __syncthreads();
        float m = red[0];
        #pragma unroll
        for (int i = 1; i < 8; i++) m = fmaxf(m, red[i]);

        float lsum = 0.f;
        for (int i = tid; i < LS_; i += 256) {
            float e = __expf(row[i] - m);
            row[i] = e;
            lsum += e;
        }
        #pragma unroll
        for (int o = 16; o; o >>= 1) lsum += __shfl_xor_sync(~0u, lsum, o);
        __syncthreads();
        if (lane == 0) red[wid] = lsum;
        __syncthreads();
        float ssum = red[0];
        #pragma unroll
        for (int i = 1; i < 8; i++) ssum += red[i];
        float inv = 1.f / ssum;

        for (int i = tid; i < LS_; i += 256) {
            float p = row[i] * inv;
            __nv_bfloat16 hi, lo;
            fsplit(p, hi, lo);
            Prow[i] = hi;
            Prow[LS_ + i] = lo;
            avg[i] += p * (1.f / (float)H_);
        }
        __syncthreads();
    }

    for (int i = tid; i < LS_; i += 256)
        avg_out[(size_t)bt * LS_ + i] = avg[i];
}

// ---------------------------------------------------------------------------
// Context HMMA: ctx[t, dd] = sum_s p[t,s] * v[s,dd], per (b,h).
// A = p planes [z,t,2,2048]; B = v planes [b,s,2,768] (k-major -> ldmatrix.trans).
// K' = 6144 -> 192 chunks. CTA 128x64, warp tile 64x16. grid (1, 4, 96).
// Epilogue writes ctx split planes at [b*512+t][2][768] + h*64.
// ---------------------------------------------------------------------------
__global__ __launch_bounds__(256) void ctx_mma(
    const __nv_bfloat16* __restrict__ P,
    const __nv_bfloat16* __restrict__ V1, const __nv_bfloat16* __restrict__ V2,
    __nv_bfloat16* __restrict__ Cs)
{
    extern __shared__ char smx[];
    const uint32_t base = smem_u32(smx);

    const int tid  = threadIdx.x;
    const int warp = tid >> 5, lane = tid & 31;
    const int wm = warp >> 2, wn = warp & 3;   // 2(M) x 4(N of 16)
    const int z = blockIdx.z;
    const int b = z / H_, h = z % H_;
    const int m0 = blockIdx.y * 128;

    // A slots: 2 per thread (512 chunks)
    const __nv_bfloat16* aRow[2];
    uint32_t offA[2];
    #pragma unroll
    for (int i = 0; i < 2; i++) {
        int idx = tid + i * 256;
        int r = idx >> 2, c8 = (idx & 3) * 8;
        aRow[i] = P + ((size_t)z * LO_ + m0 + r) * (2 * LS_) + c8;
        offA[i] = 2u * (r * PADK + c8);
    }
    // B slot: 1 per thread (256 chunks): 32 k-rows x 64 n
    const int rB = tid >> 3;
    const int cB = (tid & 7) * 8;
    const __nv_bfloat16* v1b = V1 + (size_t)b * LV_ * RS2 + h * D_ + cB;
    const __nv_bfloat16* v2b = V2 + (size_t)b * LL_ * RS2 + h * D_ + cB;
    const uint32_t offB = 2u * (rB * PADB + cB);

    #define CLOAD(j) do { \
        int _t = (j) >> 6, _ko = ((j) & 63) * 32; \
        int _ap = (_t == 1) ? LS_ : 0; \
        size_t _wp = (_t == 2) ? E_ : 0; \
        uint32_t _sb = base + ((j) & 3) * STG_CTX_B; \
        _Pragma("unroll") \
        for (int _i = 0; _i < 2; _i++) \
            cpa16(_sb + offA[_i], aRow[_i] + _ap + _ko); \
        { \
            int _sg = _ko + rB; \
            const __nv_bfloat16* _src = (_sg < LV_) \
                ? v1b + (size_t)_sg * RS2 + _wp \
                : v2b + (size_t)(_sg - LV_) * RS2 + _wp; \
            cpa16(_sb + 2 * TILE_AE + offB, _src); \
        } \
        asm volatile("cp.async.commit_group;" ::: "memory"); \
    } while (0)

    CLOAD(0); CLOAD(1); CLOAD(2);

    const int lr = lane & 15;
    const int lh = (lane >> 4) * 8;
    // trans-ldmatrix addressing for B (k x n tile)
    const int tg  = lane >> 3;          // group 0..3
    const int tlr = lane & 7;           // row within 8x8
    const int tko = (tg & 1) * 8;       // k-half of 16
    const int tno = (tg >> 1) * 8;      // n-half of 16

    float acc[4][2][4];
    #pragma unroll
    for (int i = 0; i < 4; i++)
        #pragma unroll
        for (int j = 0; j < 2; j++)
            #pragma unroll
            for (int q = 0; q < 4; q++) acc[i][j][q] = 0.f;

    const int NCHUNK = 192;
    for (int c = 0; c < NCHUNK; c++) {
        asm volatile("cp.async.wait_group 2;" ::: "memory");
        __syncthreads();
        if (c + 3 < NCHUNK) CLOAD(c + 3);
        else asm volatile("cp.async.commit_group;" ::: "memory");

        const uint32_t ab = base + (c & 3) * STG_CTX_B;
        const uint32_t bb = ab + 2 * TILE_AE;
        #pragma unroll
        for (int kf = 0; kf < 2; kf++) {
            uint32_t a[4][4];
            #pragma unroll
            for (int mi = 0; mi < 4; mi++)
                ldm_x4(a[mi][0], a[mi][1], a[mi][2], a[mi][3],
                       ab + 2u * ((wm * 64 + mi * 16 + lr) * PADK + kf * 16 + lh));
            uint32_t rb[4];
            ldm_x4_t(rb[0], rb[1], rb[2], rb[3],
                     bb + 2u * ((kf * 16 + tko + tlr) * PADB + wn * 16 + tno));
            #pragma unroll
            for (int mi = 0; mi < 4; mi++)
                #pragma unroll
                for (int nb = 0; nb < 2; nb++)
                    mma16816(acc[mi][nb], a[mi], rb[nb * 2], rb[nb * 2 + 1]);
        }
    }
    #undef CLOAD

    const int er = lane >> 2;
    const int ec = (lane & 3) * 2;
    #pragma unroll
    for (int mi = 0; mi < 4; mi++) {
        #pragma unroll
        for (int nb = 0; nb < 2; nb++) {
            int m = m0 + wm * 64 + mi * 16 + er;
            int nl = wn * 16 + nb * 8 + ec;
            __nv_bfloat16* d0 = Cs + (size_t)(b * LO_ + m) * RS2 + h * D_ + nl;
            __nv_bfloat16* d1 = Cs + (size_t)(b * LO_ + m + 8) * RS2 + h * D_ + nl;
            __nv_bfloat16 h0, l0, h1, l1;
            fsplit(acc[mi][nb][0], h0, l0); fsplit(acc[mi][nb][1], h1, l1);
            *(__nv_bfloat162*)(d0)      = __nv_bfloat162(h0, h1);
            *(__nv_bfloat162*)(d0 + E_) = __nv_bfloat162(l0, l1);
            fsplit(acc[mi][nb][2], h0, l0); fsplit(acc[mi][nb][3], h1, l1);
            *(__nv_bfloat162*)(d1)      = __nv_bfloat162(h0, h1);
            *(__nv_bfloat162*)(d1 + E_) = __nv_bfloat162(l0, l1);
        }
    }
}

// ---------------------------------------------------------------------------
// Launch
// ---------------------------------------------------------------------------
extern "C" void kernel_launch(void* const* d_in, const int* in_sizes, int n_in,
                              void* d_out, int out_size)
{
    (void)in_sizes; (void)n_in; (void)out_size;

    const float* V    = (const float*)d_in[0];
    const float* L    = (const float*)d_in[1];
    const float* O    = (const float*)d_in[2];
    const float* mask = (const float*)d_in[3];
    const float* w1   = (const float*)d_in[4];
    const float* b1   = (const float*)d_in[5];
    const float* w2   = (const float*)d_in[6];
    const float* b2   = (const float*)d_in[7];
    const float* ow   = (const float*)d_in[8];
    const float* ob   = (const float*)d_in[9];

    float* out = (float*)d_out;
    float* avg = out + (size_t)B_ * LO_ * E_;

    float* S;
    __nv_bfloat16 *Psp, *Osp, *Vsp, *Lsp, *q1sp, *q2sp, *k1sp, *v1sp, *k2sp, *v2sp,
                  *ctxsp, *w1sp, *w2sp, *owsp;
    cudaGetSymbolAddress((void**)&S,     g_S);
    cudaGetSymbolAddress((void**)&Psp,   g_Psp);
    cudaGetSymbolAddress((void**)&Osp,   g_Osp);
    cudaGetSymbolAddress((void**)&Vsp,   g_Vsp);
    cudaGetSymbolAddress((void**)&Lsp,   g_Lsp);
    cudaGetSymbolAddress((void**)&q1sp,  g_q1sp);
    cudaGetSymbolAddress((void**)&q2sp,  g_q2sp);
    cudaGetSymbolAddress((void**)&k1sp,  g_k1sp);
    cudaGetSymbolAddress((void**)&v1sp,  g_v1sp);
    cudaGetSymbolAddress((void**)&k2sp,  g_k2sp);
    cudaGetSymbolAddress((void**)&v2sp,  g_v2sp);
    cudaGetSymbolAddress((void**)&ctxsp, g_ctxsp);
    cudaGetSymbolAddress((void**)&w1sp,  g_w1sp);
    cudaGetSymbolAddress((void**)&w2sp,  g_w2sp);
    cudaGetSymbolAddress((void**)&owsp,  g_owsp);

    cudaFuncSetAttribute(gemm_proj, cudaFuncAttributeMaxDynamicSharedMemorySize, SMEM_PROJ);
    cudaFuncSetAttribute(scores_mma, cudaFuncAttributeMaxDynamicSharedMemorySize, SMEM_PROJ);
    cudaFuncSetAttribute(ctx_mma, cudaFuncAttributeMaxDynamicSharedMemorySize, SMEM_CTX);

    dim3 blk(256);

    // 1) Split inputs to 2-plane bf16
    auto cgrid = [](int rows) { return (rows * (E_ / 4) + 255) / 256; };
    split2_kernel<<<cgrid(B_ * LV_), 256>>>(V,  Vsp, B_ * LV_);
    split2_kernel<<<cgrid(B_ * LL_), 256>>>(L,  Lsp, B_ * LL_);
    split2_kernel<<<cgrid(B_ * LO_), 256>>>(O,  Osp, B_ * LO_);
    split2_kernel<<<cgrid(3 * E_),   256>>>(w1, w1sp, 3 * E_);
    split2_kernel<<<cgrid(3 * E_),   256>>>(w2, w2sp, 3 * E_);
    split2_kernel<<<cgrid(E_),       256>>>(ow, owsp, E_);

    // 2) Projections -> split-plane q/k/v
    dim3 gQ(E_ / 128, (B_ * LO_) / 128);   // 6 x 32
    dim3 gK(E_ / 128, (B_ * LV_) / 128);   // 6 x 64
    const size_t WSTRIDE = (size_t)E_ * RS2;
    gemm_proj<<<gQ, blk, SMEM_PROJ>>>(Osp, w1sp,               b1,           nullptr, q1sp, 1);
    gemm_proj<<<gQ, blk, SMEM_PROJ>>>(Osp, w2sp,               b2,           nullptr, q2sp, 1);
    gemm_proj<<<gK, blk, SMEM_PROJ>>>(Vsp, w1sp + WSTRIDE,     b1 + E_,      nullptr, k1sp, 1);
    gemm_proj<<<gK, blk, SMEM_PROJ>>>(Vsp, w1sp + 2 * WSTRIDE, b1 + 2 * E_,  nullptr, v1sp, 1);
    gemm_proj<<<gK, blk, SMEM_PROJ>>>(Lsp, w2sp + WSTRIDE,     b2 + E_,      nullptr, k2sp, 1);
    gemm_proj<<<gK, blk, SMEM_PROJ>>>(Lsp, w2sp + 2 * WSTRIDE, b2 + 2 * E_,  nullptr, v2sp, 1);

    // 3) Scores (HMMA)
    dim3 gS(LS_ / 128, LO_ / 128, Z_);     // 16 x 4 x 96
    scores_mma<<<gS, blk, SMEM_PROJ>>>(q1sp, q2sp, k1sp, k2sp, mask, S);

    // 4) Softmax + head-average, p -> split planes
    softmax_kernel<<<B_ * LO_, 256>>>(S, Psp, avg);

    // 5) Context (HMMA) -> split-plane ctx
    dim3 gC(1, LO_ / 128, Z_);             // 1 x 4 x 96
    ctx_mma<<<gC, blk, SMEM_CTX>>>(Psp, v1sp, v2sp, ctxsp);

    // 6) Output projection (fp32 out + bias)
    gemm_proj<<<gQ, blk, SMEM_PROJ>>>(ctxsp, owsp, ob, out, nullptr, 0);
}

// round 5
// speedup vs baseline: 2.1684x; 1.2589x over previous
#include <cuda_runtime.h>
#include <cuda_bf16.h>
#include <cuda_fp16.h>
#include <math.h>
#include <stdint.h>

// Problem dims
#define E_  768
#define H_  12
#define D_  64
#define B_  8
#define LO_ 512
#define LV_ 1024
#define LL_ 1024
#define LS_ 2048
#define Z_  (B_ * H_)     // 96
#define E2_ 1536          // fused qq/kv column count

#define PADK 40           // padded 32-K-chunk row stride (elems)
#define PADB 72           // padded ctx-B / scores row stride (elems)
#define TILE_AE (128 * PADK)
#define STG_PROJ_B (2 * TILE_AE * 2)             // 20480 B per stage
#define STG_CTX_B (TILE_AE * 2 + 32 * PADB * 2)  // 14848
#define SMEM_PROJ (4 * STG_PROJ_B)               // 81920
#define SMEM_CTX  (4 * STG_CTX_B)                // 59392
#define RS2 (2 * E_)      // bf16 2-plane row stride

// ---------------------------------------------------------------------------
// Scratch
// ---------------------------------------------------------------------------
__device__ __nv_bfloat16 g_Osp [(size_t)B_ * LO_ * RS2];
__device__ __nv_bfloat16 g_Vsp [(size_t)B_ * LV_ * RS2];
__device__ __nv_bfloat16 g_Lsp [(size_t)B_ * LL_ * RS2];
__device__ __nv_bfloat16 g_ctxsp[(size_t)B_ * LO_ * RS2];
__device__ __nv_bfloat16 g_w1sp[(size_t)(3 * E_) * RS2];
__device__ __nv_bfloat16 g_w2sp[(size_t)(3 * E_) * RS2];
__device__ __nv_bfloat16 g_owsp[(size_t)E_ * RS2];

__device__ __half g_qq [(size_t)B_ * LO_ * E2_];   // [q1 | q2]
__device__ __half g_kv1[(size_t)B_ * LV_ * E2_];   // [k1 | v1]
__device__ __half g_kv2[(size_t)B_ * LL_ * E2_];   // [k2 | v2]
__device__ __half g_Sh [(size_t)Z_ * LO_ * LS_];   // scores fp16
__device__ __half g_Ph [(size_t)Z_ * LO_ * LS_];   // probs fp16

// ---------------------------------------------------------------------------
// Helpers
// ---------------------------------------------------------------------------
__device__ __forceinline__ uint32_t smem_u32(const void* p) {
    uint32_t a;
    asm("{ .reg .u64 t; cvta.to.shared.u64 t, %1; cvt.u32.u64 %0, t; }"
        : "=r"(a) : "l"(p));
    return a;
}
__device__ __forceinline__ void cpa16(uint32_t s, const void* g) {
    asm volatile("cp.async.cg.shared.global [%0], [%1], 16;" :: "r"(s), "l"(g));
}
__device__ __forceinline__ void ldm_x4(uint32_t& r0, uint32_t& r1, uint32_t& r2,
                                       uint32_t& r3, uint32_t addr) {
    asm volatile("ldmatrix.sync.aligned.m8n8.x4.shared.b16 {%0,%1,%2,%3}, [%4];"
        : "=r"(r0), "=r"(r1), "=r"(r2), "=r"(r3) : "r"(addr));
}
__device__ __forceinline__ void ldm_x4_t(uint32_t& r0, uint32_t& r1, uint32_t& r2,
                                         uint32_t& r3, uint32_t addr) {
    asm volatile("ldmatrix.sync.aligned.m8n8.x4.trans.shared.b16 {%0,%1,%2,%3}, [%4];"
        : "=r"(r0), "=r"(r1), "=r"(r2), "=r"(r3) : "r"(addr));
}
__device__ __forceinline__ void mma_bf(float* d, const uint32_t* a,
                                       uint32_t b0, uint32_t b1) {
    asm volatile(
        "mma.sync.aligned.m16n8k16.row.col.f32.bf16.bf16.f32 "
        "{%0,%1,%2,%3}, {%4,%5,%6,%7}, {%8,%9}, {%0,%1,%2,%3};"
        : "+f"(d[0]), "+f"(d[1]), "+f"(d[2]), "+f"(d[3])
        : "r"(a[0]), "r"(a[1]), "r"(a[2]), "r"(a[3]), "r"(b0), "r"(b1));
}
__device__ __forceinline__ void mma_hf(float* d, const uint32_t* a,
                                       uint32_t b0, uint32_t b1) {
    asm volatile(
        "mma.sync.aligned.m16n8k16.row.col.f32.f16.f16.f32 "
        "{%0,%1,%2,%3}, {%4,%5,%6,%7}, {%8,%9}, {%0,%1,%2,%3};"
        : "+f"(d[0]), "+f"(d[1]), "+f"(d[2]), "+f"(d[3])
        : "r"(a[0]), "r"(a[1]), "r"(a[2]), "r"(a[3]), "r"(b0), "r"(b1));
}
__device__ __forceinline__ void fsplit(float x, __nv_bfloat16& h, __nv_bfloat16& l) {
    h = __float2bfloat16(x);
    l = __float2bfloat16(x - __bfloat162float(h));
}

// ---------------------------------------------------------------------------
// Split-2: x[r,768] fp32 -> y[r,2,768] bf16 (hi, lo planes)
// ---------------------------------------------------------------------------
__global__ __launch_bounds__(256) void split2_kernel(
    const float* __restrict__ x, __nv_bfloat16* __restrict__ y, int nrows)
{
    int gid = blockIdx.x * 256 + threadIdx.x;
    int total = nrows * (E_ / 4);
    if (gid >= total) return;
    int r = gid / (E_ / 4);
    int c4 = (gid % (E_ / 4)) * 4;
    float4 v = *(const float4*)(x + (size_t)r * E_ + c4);
    float vv[4] = {v.x, v.y, v.z, v.w};
    uint64_t hp = 0, lp = 0;
    #pragma unroll
    for (int i = 0; i < 4; i++) {
        __nv_bfloat16 hi, lo;
        fsplit(vv[i], hi, lo);
        hp |= (uint64_t)__bfloat16_as_ushort(hi) << (16 * i);
        lp |= (uint64_t)__bfloat16_as_ushort(lo) << (16 * i);
    }
    __nv_bfloat16* row = y + (size_t)r * RS2 + c4;
    *(uint64_t*)(row)      = hp;
    *(uint64_t*)(row + E_) = lp;
}

// ---------------------------------------------------------------------------
// Projection GEMM (bf16 3-term split, K'=2304): C[m,n] = A·W^T + bias
// W rows n<768 from W1, n>=768 from W2 (fused dual-output launches).
// outmode 0: fp32 out (ldc=768). outmode 2: fp16 out (ldc=1536).
// ---------------------------------------------------------------------------
__global__ __launch_bounds__(256) void gemm_proj(
    const __nv_bfloat16* __restrict__ A,
    const __nv_bfloat16* __restrict__ W1,
    const __nv_bfloat16* __restrict__ W2,
    const float* __restrict__ bias1,
    const float* __restrict__ bias2,
    float* __restrict__ Cf,
    __half* __restrict__ Ch,
    int outmode)
{
    extern __shared__ char smx[];
    const uint32_t base = smem_u32(smx);

    const int tid  = threadIdx.x;
    const int warp = tid >> 5, lane = tid & 31;
    const int wm = warp >> 2, wn = warp & 3;
    const int m0 = blockIdx.y * 128;
    const int n0 = blockIdx.x * 128;

    const __nv_bfloat16* Wb = (n0 < E_) ? W1 + (size_t)n0 * RS2
                                        : W2 + (size_t)(n0 - E_) * RS2;
    const float* biasb = (n0 < E_) ? bias1 + n0 : bias2 + (n0 - E_);

    const __nv_bfloat16* aRow[2];
    const __nv_bfloat16* wRow[2];
    uint32_t offS[2];
    #pragma unroll
    for (int i = 0; i < 2; i++) {
        int idx = tid + i * 256;
        int r = idx >> 2, c8 = (idx & 3) * 8;
        aRow[i] = A + (size_t)(m0 + r) * RS2 + c8;
        wRow[i] = Wb + (size_t)r * RS2 + c8;
        offS[i] = 2u * (r * PADK + c8);
    }

    #define PLOAD(j) do { \
        int _t = (j) / 24, _ko = ((j) % 24) * 32; \
        int _ap = (_t == 1) ? E_ : 0, _wp = (_t == 2) ? E_ : 0; \
        uint32_t _sb = base + ((j) & 3) * STG_PROJ_B; \
        _Pragma("unroll") \
        for (int _i = 0; _i < 2; _i++) { \
            cpa16(_sb + offS[_i], aRow[_i] + _ap + _ko); \
            cpa16(_sb + 2 * TILE_AE + offS[_i], wRow[_i] + _wp + _ko); \
        } \
        asm volatile("cp.async.commit_group;" ::: "memory"); \
    } while (0)

    PLOAD(0); PLOAD(1); PLOAD(2);

    const int lr = lane & 15;
    const int lh = (lane >> 4) * 8;

    float acc[4][4][4];
    #pragma unroll
    for (int i = 0; i < 4; i++)
        #pragma unroll
        for (int j = 0; j < 4; j++)
            #pragma unroll
            for (int q = 0; q < 4; q++) acc[i][j][q] = 0.f;

    const int NCHUNK = 72;
    for (int c = 0; c < NCHUNK; c++) {
        asm volatile("cp.async.wait_group 2;" ::: "memory");
        __syncthreads();
        if (c + 3 < NCHUNK) PLOAD(c + 3);
        else asm volatile("cp.async.commit_group;" ::: "memory");

        const uint32_t ab = base + (c & 3) * STG_PROJ_B;
        const uint32_t bb = ab + 2 * TILE_AE;
        #pragma unroll
        for (int kf = 0; kf < 2; kf++) {
            uint32_t a[4][4];
            #pragma unroll
            for (int mi = 0; mi < 4; mi++)
                ldm_x4(a[mi][0], a[mi][1], a[mi][2], a[mi][3],
                       ab + 2u * ((wm * 64 + mi * 16 + lr) * PADK + kf * 16 + lh));
            uint32_t br[2][4];
            #pragma unroll
            for (int g = 0; g < 2; g++)
                ldm_x4(br[g][0], br[g][1], br[g][2], br[g][3],
                       bb + 2u * ((wn * 32 + g * 16 + lr) * PADK + kf * 16 + lh));
            #pragma unroll
            for (int mi = 0; mi < 4; mi++)
                #pragma unroll
                for (int g = 0; g < 2; g++)
                    #pragma unroll
                    for (int s = 0; s < 2; s++)
                        mma_bf(acc[mi][g * 2 + s], a[mi], br[g][s], br[g][s + 2]);
        }
    }
    #undef PLOAD

    const int er = lane >> 2;
    const int ec = (lane & 3) * 2;
    #pragma unroll
    for (int mi = 0; mi < 4; mi++) {
        #pragma unroll
        for (int ni = 0; ni < 4; ni++) {
            int m = m0 + wm * 64 + mi * 16 + er;
            int cl = wn * 32 + ni * 8 + ec;        // local col 0..127
            float bx = __ldg(biasb + cl), by = __ldg(biasb + cl + 1);
            float v00 = acc[mi][ni][0] + bx, v01 = acc[mi][ni][1] + by;
            float v10 = acc[mi][ni][2] + bx, v11 = acc[mi][ni][3] + by;
            if (outmode == 2) {
                __half2 h0 = __floats2half2_rn(v00, v01);
                __half2 h1 = __floats2half2_rn(v10, v11);
                *(__half2*)(Ch + (size_t)m * E2_ + n0 + cl)       = h0;
                *(__half2*)(Ch + (size_t)(m + 8) * E2_ + n0 + cl) = h1;
            } else {
                *(float2*)(Cf + (size_t)m * E_ + n0 + cl)       = make_float2(v00, v01);
                *(float2*)(Cf + (size_t)(m + 8) * E_ + n0 + cl) = make_float2(v10, v11);
            }
        }
    }
}

// ---------------------------------------------------------------------------
// Scores (fp16 HMMA, K=64): S[z,t,s] = 0.125*<q,k> + mask[t,s], fp16 out.
// grid (16, 4, 96), CTA 128x128.
// ---------------------------------------------------------------------------
__global__ __launch_bounds__(256) void scores_mma(
    const __half* __restrict__ Q, const __half* __restrict__ KV1,
    const __half* __restrict__ KV2,
    const float* __restrict__ mask, __half* __restrict__ S)
{
    __shared__ __align__(16) __half As[128 * PADB];
    __shared__ __align__(16) __half Bs[128 * PADB];

    const int tid  = threadIdx.x;
    const int warp = tid >> 5, lane = tid & 31;
    const int wm = warp >> 2, wn = warp & 3;
    const int z = blockIdx.z;
    const int b = z / H_, h = z % H_;
    const int m0 = blockIdx.y * 128;
    const int n0 = blockIdx.x * 128;
    const bool src2 = (n0 >= LV_);
    const int sr0 = src2 ? n0 - LV_ : n0;
    const __half* kv = src2 ? KV2 : KV1;
    const int qoff = (src2 ? E_ : 0) + h * D_;

    const uint32_t baseA = smem_u32(As);
    const uint32_t baseB = smem_u32(Bs);

    #pragma unroll
    for (int i = 0; i < 4; i++) {
        int idx = tid + i * 256;
        int r = idx >> 3, c = (idx & 7) * 8;
        cpa16(baseA + 2u * (r * PADB + c),
              Q + (size_t)(b * LO_ + m0 + r) * E2_ + qoff + c);
        cpa16(baseB + 2u * (r * PADB + c),
              kv + (size_t)(b * LV_ + sr0 + r) * E2_ + h * D_ + c);
    }
    asm volatile("cp.async.commit_group;" ::: "memory");
    asm volatile("cp.async.wait_group 0;" ::: "memory");
    __syncthreads();

    const int lr = lane & 15;
    const int lh = (lane >> 4) * 8;

    float acc[4][4][4];
    #pragma unroll
    for (int i = 0; i < 4; i++)
        #pragma unroll
        for (int j = 0; j < 4; j++)
            #pragma unroll
            for (int q = 0; q < 4; q++) acc[i][j][q] = 0.f;

    #pragma unroll
    for (int kf = 0; kf < 4; kf++) {
        uint32_t a[4][4];
        #pragma unroll
        for (int mi = 0; mi < 4; mi++)
            ldm_x4(a[mi][0], a[mi][1], a[mi][2], a[mi][3],
                   baseA + 2u * ((wm * 64 + mi * 16 + lr) * PADB + kf * 16 + lh));
        uint32_t br[2][4];
        #pragma unroll
        for (int g = 0; g < 2; g++)
            ldm_x4(br[g][0], br[g][1], br[g][2], br[g][3],
                   baseB + 2u * ((wn * 32 + g * 16 + lr) * PADB + kf * 16 + lh));
        #pragma unroll
        for (int mi = 0; mi < 4; mi++)
            #pragma unroll
            for (int g = 0; g < 2; g++)
                #pragma unroll
                for (int s = 0; s < 2; s++)
                    mma_hf(acc[mi][g * 2 + s], a[mi], br[g][s], br[g][s + 2]);
    }

    const int er = lane >> 2;
    const int ec = (lane & 3) * 2;
    #pragma unroll
    for (int mi = 0; mi < 4; mi++) {
        #pragma unroll
        for (int ni = 0; ni < 4; ni++) {
            int m = m0 + wm * 64 + mi * 16 + er;
            int n = n0 + wn * 32 + ni * 8 + ec;
            float2 mk0 = *(const float2*)(mask + (size_t)m * LS_ + n);
            float2 mk1 = *(const float2*)(mask + (size_t)(m + 8) * LS_ + n);
            __half2 o0 = __floats2half2_rn(acc[mi][ni][0] * 0.125f + mk0.x,
                                           acc[mi][ni][1] * 0.125f + mk0.y);
            __half2 o1 = __floats2half2_rn(acc[mi][ni][2] * 0.125f + mk1.x,
                                           acc[mi][ni][3] * 0.125f + mk1.y);
            *(__half2*)(S + ((size_t)z * LO_ + m) * LS_ + n)     = o0;
            *(__half2*)(S + ((size_t)z * LO_ + m + 8) * LS_ + n) = o1;
        }
    }
}

// ---------------------------------------------------------------------------
// Softmax: S fp16 -> P fp16 + head-average (fp32 out).
// ---------------------------------------------------------------------------
__global__ __launch_bounds__(256) void softmax_kernel(
    const __half* __restrict__ S, __half* __restrict__ P,
    float* __restrict__ avg_out)
{
    __shared__ float row[LS_];
    __shared__ float avg[LS_];
    __shared__ float red[8];

    const int bt = blockIdx.x;
    const int b = bt / LO_, t = bt % LO_;
    const int tid = threadIdx.x;
    const int lane = tid & 31, wid = tid >> 5;

    for (int i = tid; i < LS_; i += 256) avg[i] = 0.f;

    for (int h = 0; h < H_; h++) {
        const __half* Srow = S + (((size_t)(b * H_ + h)) * LO_ + t) * LS_;
        __half* Prow = P + (((size_t)(b * H_ + h)) * LO_ + t) * LS_;

        float lmax = -1e30f;
        for (int i = tid; i < LS_ / 2; i += 256) {
            float2 v = __half22float2(*((const __half2*)Srow + i));
            row[2 * i] = v.x;
            row[2 * i + 1] = v.y;
            lmax = fmaxf(lmax, fmaxf(v.x, v.y));
        }
        #pragma unroll
        for (int o = 16; o; o >>= 1) lmax = fmaxf(lmax, __shfl_xor_sync(~0u, lmax, o));
        if (lane == 0) red[wid] = lmax;
        __syncthreads();
        float m = red[0];
        #pragma unroll
        for (int i = 1; i < 8; i++) m = fmaxf(m, red[i]);

        float lsum = 0.f;
        for (int i = tid; i < LS_; i += 256) {
            float e = __expf(row[i] - m);
            row[i] = e;
            lsum += e;
        }
        #pragma unroll
        for (int o = 16; o; o >>= 1) lsum += __shfl_xor_sync(~0u, lsum, o);
        __syncthreads();
        if (lane == 0) red[wid] = lsum;
        __syncthreads();
        float ssum = red[0];
        #pragma unroll
        for (int i = 1; i < 8; i++) ssum += red[i];
        float inv = 1.f / ssum;

        for (int i = tid; i < LS_ / 2; i += 256) {
            float p0 = row[2 * i] * inv;
            float p1 = row[2 * i + 1] * inv;
            *((__half2*)Prow + i) = __floats2half2_rn(p0, p1);
            avg[2 * i]     += p0 * (1.f / (float)H_);
            avg[2 * i + 1] += p1 * (1.f / (float)H_);
        }
        __syncthreads();
    }

    for (int i = tid; i < LS_; i += 256)
        avg_out[(size_t)bt * LS_ + i] = avg[i];
}

// ---------------------------------------------------------------------------
// Context (fp16 HMMA, K=2048): ctx[t,dd] = sum_s p[t,s] v[s,dd] per (b,h).
// Output: bf16 hi/lo planes into ctxsp. grid (1, 4, 96), CTA 128x64.
// ---------------------------------------------------------------------------
__global__ __launch_bounds__(256) void ctx_mma(
    const __half* __restrict__ P,
    const __half* __restrict__ KV1, const __half* __restrict__ KV2,
    __nv_bfloat16* __restrict__ Cs)
{
    extern __shared__ char smx[];
    const uint32_t base = smem_u32(smx);

    const int tid  = threadIdx.x;
    const int warp = tid >> 5, lane = tid & 31;
    const int wm = warp >> 2, wn = warp & 3;
    const int z = blockIdx.z;
    const int b = z / H_, h = z % H_;
    const int m0 = blockIdx.y * 128;

    const __half* aRow[2];
    uint32_t offA[2];
    #pragma unroll
    for (int i = 0; i < 2; i++) {
        int idx = tid + i * 256;
        int r = idx >> 2, c8 = (idx & 3) * 8;
        aRow[i] = P + ((size_t)z * LO_ + m0 + r) * LS_ + c8;
        offA[i] = 2u * (r * PADK + c8);
    }
    const int rB = tid >> 3;
    const int cB = (tid & 7) * 8;
    const __half* v1b = KV1 + (size_t)b * LV_ * E2_ + E_ + h * D_ + cB;
    const __half* v2b = KV2 + (size_t)b * LL_ * E2_ + E_ + h * D_ + cB;
    const uint32_t offB = 2u * (rB * PADB + cB);

    #define CLOAD(j) do { \
        int _ko = (j) * 32; \
        uint32_t _sb = base + ((j) & 3) * STG_CTX_B; \
        _Pragma("unroll") \
        for (int _i = 0; _i < 2; _i++) \
            cpa16(_sb + offA[_i], aRow[_i] + _ko); \
        { \
            int _sg = _ko + rB; \
            const __half* _src = (_sg < LV_) \
                ? v1b + (size_t)_sg * E2_ \
                : v2b + (size_t)(_sg - LV_) * E2_; \
            cpa16(_sb + 2 * TILE_AE + offB, _src); \
        } \
        asm volatile("cp.async.commit_group;" ::: "memory"); \
    } while (0)

    CLOAD(0); CLOAD(1); CLOAD(2);

    const int lr = lane & 15;
    const int lh = (lane >> 4) * 8;
    const int tg  = lane >> 3;
    const int tlr = lane & 7;
    const int tko = (tg & 1) * 8;
    const int tno = (tg >> 1) * 8;

    float acc[4][2][4];
    #pragma unroll
    for (int i = 0; i < 4; i++)
        #pragma unroll
        for (int j = 0; j < 2; j++)
            #pragma unroll
            for (int q = 0; q < 4; q++) acc[i][j][q] = 0.f;

    const int NCHUNK = 64;
    for (int c = 0; c < NCHUNK; c++) {
        asm volatile("cp.async.wait_group 2;" ::: "memory");
        __syncthreads();
        if (c + 3 < NCHUNK) CLOAD(c + 3);
        else asm volatile("cp.async.commit_group;" ::: "memory");

        const uint32_t ab = base + (c & 3) * STG_CTX_B;
        const uint32_t bb = ab + 2 * TILE_AE;
        #pragma unroll
        for (int kf = 0; kf < 2; kf++) {
            uint32_t a[4][4];
            #pragma unroll
            for (int mi = 0; mi < 4; mi++)
                ldm_x4(a[mi][0], a[mi][1], a[mi][2], a[mi][3],
                       ab + 2u * ((wm * 64 + mi * 16 + lr) * PADK + kf * 16 + lh));
            uint32_t rb[4];
            ldm_x4_t(rb[0], rb[1], rb[2], rb[3],
                     bb + 2u * ((kf * 16 + tko + tlr) * PADB + wn * 16 + tno));
            #pragma unroll
            for (int mi = 0; mi < 4; mi++)
                #pragma unroll
                for (int nb = 0; nb < 2; nb++)
                    mma_hf(acc[mi][nb], a[mi], rb[nb * 2], rb[nb * 2 + 1]);
        }
    }
    #undef CLOAD

    const int er = lane >> 2;
    const int ec = (lane & 3) * 2;
    #pragma unroll
    for (int mi = 0; mi < 4; mi++) {
        #pragma unroll
        for (int nb = 0; nb < 2; nb++) {
            int m = m0 + wm * 64 + mi * 16 + er;
            int nl = wn * 16 + nb * 8 + ec;
            __nv_bfloat16* d0 = Cs + (size_t)(b * LO_ + m) * RS2 + h * D_ + nl;
            __nv_bfloat16* d1 = Cs + (size_t)(b * LO_ + m + 8) * RS2 + h * D_ + nl;
            __nv_bfloat16 h0, l0, h1, l1;
            fsplit(acc[mi][nb][0], h0, l0); fsplit(acc[mi][nb][1], h1, l1);
            *(__nv_bfloat162*)(d0)      = __nv_bfloat162(h0, h1);
            *(__nv_bfloat162*)(d0 + E_) = __nv_bfloat162(l0, l1);
            fsplit(acc[mi][nb][2], h0, l0); fsplit(acc[mi][nb][3], h1, l1);
            *(__nv_bfloat162*)(d1)      = __nv_bfloat162(h0, h1);
            *(__nv_bfloat162*)(d1 + E_) = __nv_bfloat162(l0, l1);
        }
    }
}

// ---------------------------------------------------------------------------
// Launch
// ---------------------------------------------------------------------------
extern "C" void kernel_launch(void* const* d_in, const int* in_sizes, int n_in,
                              void* d_out, int out_size)
{
    (void)in_sizes; (void)n_in; (void)out_size;

    const float* V    = (const float*)d_in[0];
    const float* L    = (const float*)d_in[1];
    const float* O    = (const float*)d_in[2];
    const float* mask = (const float*)d_in[3];
    const float* w1   = (const float*)d_in[4];
    const float* b1   = (const float*)d_in[5];
    const float* w2   = (const float*)d_in[6];
    const float* b2   = (const float*)d_in[7];
    const float* ow   = (const float*)d_in[8];
    const float* ob   = (const float*)d_in[9];

    float* out = (float*)d_out;
    float* avg = out + (size_t)B_ * LO_ * E_;

    __nv_bfloat16 *Osp, *Vsp, *Lsp, *ctxsp, *w1sp, *w2sp, *owsp;
    __half *qq, *kv1, *kv2, *Sh, *Ph;
    cudaGetSymbolAddress((void**)&Osp,   g_Osp);
    cudaGetSymbolAddress((void**)&Vsp,   g_Vsp);
    cudaGetSymbolAddress((void**)&Lsp,   g_Lsp);
    cudaGetSymbolAddress((void**)&ctxsp, g_ctxsp);
    cudaGetSymbolAddress((void**)&w1sp,  g_w1sp);
    cudaGetSymbolAddress((void**)&w2sp,  g_w2sp);
    cudaGetSymbolAddress((void**)&owsp,  g_owsp);
    cudaGetSymbolAddress((void**)&qq,    g_qq);
    cudaGetSymbolAddress((void**)&kv1,   g_kv1);
    cudaGetSymbolAddress((void**)&kv2,   g_kv2);
    cudaGetSymbolAddress((void**)&Sh,    g_Sh);
    cudaGetSymbolAddress((void**)&Ph,    g_Ph);

    cudaFuncSetAttribute(gemm_proj, cudaFuncAttributeMaxDynamicSharedMemorySize, SMEM_PROJ);
    cudaFuncSetAttribute(ctx_mma, cudaFuncAttributeMaxDynamicSharedMemorySize, SMEM_CTX);

    dim3 blk(256);

    // 1) bf16 hi/lo splits
    auto cgrid = [](int rows) { return (rows * (E_ / 4) + 255) / 256; };
    split2_kernel<<<cgrid(B_ * LV_), 256>>>(V,  Vsp, B_ * LV_);
    split2_kernel<<<cgrid(B_ * LL_), 256>>>(L,  Lsp, B_ * LL_);
    split2_kernel<<<cgrid(B_ * LO_), 256>>>(O,  Osp, B_ * LO_);
    split2_kernel<<<cgrid(3 * E_),   256>>>(w1, w1sp, 3 * E_);
    split2_kernel<<<cgrid(3 * E_),   256>>>(w2, w2sp, 3 * E_);
    split2_kernel<<<cgrid(E_),       256>>>(ow, owsp, E_);

    // 2) Fused projections -> fp16 [q1|q2], [k1|v1], [k2|v2]
    const size_t WS = (size_t)E_ * RS2;
    dim3 gQQ(E2_ / 128, (B_ * LO_) / 128);   // 12 x 32
    dim3 gKV(E2_ / 128, (B_ * LV_) / 128);   // 12 x 64
    gemm_proj<<<gQQ, blk, SMEM_PROJ>>>(Osp, w1sp,        w2sp,          b1,           b2,
                                       nullptr, qq, 2);
    gemm_proj<<<gKV, blk, SMEM_PROJ>>>(Vsp, w1sp + WS,   w1sp + 2 * WS, b1 + E_,      b1 + 2 * E_,
                                       nullptr, kv1, 2);
    gemm_proj<<<gKV, blk, SMEM_PROJ>>>(Lsp, w2sp + WS,   w2sp + 2 * WS, b2 + E_,      b2 + 2 * E_,
                                       nullptr, kv2, 2);

    // 3) Scores (fp16, K=64)
    dim3 gS(LS_ / 128, LO_ / 128, Z_);       // 16 x 4 x 96
    scores_mma<<<gS, blk>>>(qq, kv1, kv2, mask, Sh);

    // 4) Softmax + head-average
    softmax_kernel<<<B_ * LO_, 256>>>(Sh, Ph, avg);

    // 5) Context (fp16, K=2048) -> bf16 split ctx
    dim3 gC(1, LO_ / 128, Z_);               // 1 x 4 x 96
    ctx_mma<<<gC, blk, SMEM_CTX>>>(Ph, kv1, kv2, ctxsp);

    // 6) Output projection (bf16 3-term, fp32 out)
    dim3 gO(E_ / 128, (B_ * LO_) / 128);     // 6 x 32
    gemm_proj<<<gO, blk, SMEM_PROJ>>>(ctxsp, owsp, owsp, ob, ob, out, nullptr, 0);
}

// round 6
// speedup vs baseline: 2.7647x; 1.2750x over previous
#include <cuda_runtime.h>
#include <cuda_bf16.h>
#include <cuda_fp16.h>
#include <math.h>
#include <stdint.h>

// Problem dims
#define E_  768
#define H_  12
#define D_  64
#define B_  8
#define LO_ 512
#define LV_ 1024
#define LL_ 1024
#define LS_ 2048
#define Z_  (B_ * H_)     // 96
#define E2_ 1536

#define PADC 72                          // padded row stride for 64-wide chunks
#define TILE64B (128 * PADC * 2)         // 18432 B: one 128x64 tile
#define STGP (2 * TILE64B)               // proj stage: A + B = 36864
#define SMEM_PROJ (3 * STGP)             // 110592
#define CTXB (64 * PADC * 2)             // 9216: ctx B tile 64x64
#define STGC (TILE64B + CTXB)            // 27648
#define SMEM_CTX (3 * STGC)              // 82944
#define RS2 (2 * E_)                     // bf16 2-plane row stride

// ---------------------------------------------------------------------------
// Scratch
// ---------------------------------------------------------------------------
__device__ __nv_bfloat16 g_Osp [(size_t)B_ * LO_ * RS2];
__device__ __nv_bfloat16 g_Vsp [(size_t)B_ * LV_ * RS2];
__device__ __nv_bfloat16 g_Lsp [(size_t)B_ * LL_ * RS2];
__device__ __nv_bfloat16 g_ctxsp[(size_t)B_ * LO_ * RS2];
__device__ __nv_bfloat16 g_w1sp[(size_t)(3 * E_) * RS2];
__device__ __nv_bfloat16 g_w2sp[(size_t)(3 * E_) * RS2];
__device__ __nv_bfloat16 g_owsp[(size_t)E_ * RS2];

__device__ __half g_qq [(size_t)B_ * LO_ * E2_];   // [q1 | q2]
__device__ __half g_kv1[(size_t)B_ * LV_ * E2_];   // [k1 | v1]
__device__ __half g_kv2[(size_t)B_ * LL_ * E2_];   // [k2 | v2]
__device__ __half g_Sh [(size_t)Z_ * LO_ * LS_];
__device__ __half g_Ph [(size_t)Z_ * LO_ * LS_];

// ---------------------------------------------------------------------------
// Helpers
// ---------------------------------------------------------------------------
__device__ __forceinline__ uint32_t smem_u32(const void* p) {
    uint32_t a;
    asm("{ .reg .u64 t; cvta.to.shared.u64 t, %1; cvt.u32.u64 %0, t; }"
        : "=r"(a) : "l"(p));
    return a;
}
__device__ __forceinline__ void cpa16(uint32_t s, const void* g) {
    asm volatile("cp.async.cg.shared.global [%0], [%1], 16;" :: "r"(s), "l"(g));
}
__device__ __forceinline__ void ldm_x4(uint32_t& r0, uint32_t& r1, uint32_t& r2,
                                       uint32_t& r3, uint32_t addr) {
    asm volatile("ldmatrix.sync.aligned.m8n8.x4.shared.b16 {%0,%1,%2,%3}, [%4];"
        : "=r"(r0), "=r"(r1), "=r"(r2), "=r"(r3) : "r"(addr));
}
__device__ __forceinline__ void ldm_x4_t(uint32_t& r0, uint32_t& r1, uint32_t& r2,
                                         uint32_t& r3, uint32_t addr) {
    asm volatile("ldmatrix.sync.aligned.m8n8.x4.trans.shared.b16 {%0,%1,%2,%3}, [%4];"
        : "=r"(r0), "=r"(r1), "=r"(r2), "=r"(r3) : "r"(addr));
}
__device__ __forceinline__ void mma_bf(float* d, const uint32_t* a,
                                       uint32_t b0, uint32_t b1) {
    asm volatile(
        "mma.sync.aligned.m16n8k16.row.col.f32.bf16.bf16.f32 "
        "{%0,%1,%2,%3}, {%4,%5,%6,%7}, {%8,%9}, {%0,%1,%2,%3};"
        : "+f"(d[0]), "+f"(d[1]), "+f"(d[2]), "+f"(d[3])
        : "r"(a[0]), "r"(a[1]), "r"(a[2]), "r"(a[3]), "r"(b0), "r"(b1));
}
__device__ __forceinline__ void mma_hf(float* d, const uint32_t* a,
                                       uint32_t b0, uint32_t b1) {
    asm volatile(
        "mma.sync.aligned.m16n8k16.row.col.f32.f16.f16.f32 "
        "{%0,%1,%2,%3}, {%4,%5,%6,%7}, {%8,%9}, {%0,%1,%2,%3};"
        : "+f"(d[0]), "+f"(d[1]), "+f"(d[2]), "+f"(d[3])
        : "r"(a[0]), "r"(a[1]), "r"(a[2]), "r"(a[3]), "r"(b0), "r"(b1));
}
__device__ __forceinline__ void fsplit(float x, __nv_bfloat16& h, __nv_bfloat16& l) {
    h = __float2bfloat16(x);
    l = __float2bfloat16(x - __bfloat162float(h));
}

// ---------------------------------------------------------------------------
// Fused split: all six fp32->bf16 hi/lo plane conversions in one launch.
// ---------------------------------------------------------------------------
#define RV 8192
#define RL 16384
#define RO 20480
#define RW1 22784
#define RW2 25088
#define ROW 25856
__global__ __launch_bounds__(256) void split_all(
    const float* __restrict__ V, const float* __restrict__ L,
    const float* __restrict__ O, const float* __restrict__ w1,
    const float* __restrict__ w2, const float* __restrict__ ow,
    __nv_bfloat16* __restrict__ Vsp, __nv_bfloat16* __restrict__ Lsp,
    __nv_bfloat16* __restrict__ Osp, __nv_bfloat16* __restrict__ w1sp,
    __nv_bfloat16* __restrict__ w2sp, __nv_bfloat16* __restrict__ owsp)
{
    const int CP = E_ / 4;
    int gid = blockIdx.x * 256 + threadIdx.x;
    int r = gid / CP, c4 = (gid % CP) * 4;
    const float* x; __nv_bfloat16* y;
    if      (r < RV)  { x = V;  y = Vsp; }
    else if (r < RL)  { x = L;  y = Lsp;  r -= RV; }
    else if (r < RO)  { x = O;  y = Osp;  r -= RL; }
    else if (r < RW1) { x = w1; y = w1sp; r -= RO; }
    else if (r < RW2) { x = w2; y = w2sp; r -= RW1; }
    else if (r < ROW) { x = ow; y = owsp; r -= RW2; }
    else return;
    float4 v = *(const float4*)(x + (size_t)r * E_ + c4);
    float vv[4] = {v.x, v.y, v.z, v.w};
    uint64_t hp = 0, lp = 0;
    #pragma unroll
    for (int i = 0; i < 4; i++) {
        __nv_bfloat16 hi, lo;
        fsplit(vv[i], hi, lo);
        hp |= (uint64_t)__bfloat16_as_ushort(hi) << (16 * i);
        lp |= (uint64_t)__bfloat16_as_ushort(lo) << (16 * i);
    }
    __nv_bfloat16* row = y + (size_t)r * RS2 + c4;
    *(uint64_t*)(row)      = hp;
    *(uint64_t*)(row + E_) = lp;
}

// ---------------------------------------------------------------------------
// Projection GEMM body (bf16 3-term split, K'=2304, K-chunk 64, 3 stages).
// OUT==0: fp32 out ldc=E_; OUT==2: fp16 out ldc=E2_.
// ---------------------------------------------------------------------------
template <int OUT>
__device__ __forceinline__ void proj_body(
    const __nv_bfloat16* __restrict__ A,
    const __nv_bfloat16* __restrict__ Wb,
    const float* __restrict__ biasb,
    float* __restrict__ Cf, __half* __restrict__ Ch,
    int m0, int n0, char* smx)
{
    const uint32_t base = smem_u32(smx);
    const int tid  = threadIdx.x;
    const int warp = tid >> 5, lane = tid & 31;
    const int wm = warp >> 2, wn = warp & 3;

    const int rA = tid >> 3;            // 0..31
    const int c8 = (tid & 7) * 8;       // 0..56
    const __nv_bfloat16* aP = A + (size_t)(m0 + rA) * RS2 + c8;
    const __nv_bfloat16* wP = Wb + (size_t)rA * RS2 + c8;
    const uint32_t off0 = 2u * (rA * PADC + c8);

    #define PLOAD(j) do { \
        int _t = (j) / 12, _ko = ((j) % 12) * 64; \
        int _ap = (_t == 1) ? E_ : 0, _wp = (_t == 2) ? E_ : 0; \
        uint32_t _sb = base + ((j) % 3) * STGP; \
        _Pragma("unroll") \
        for (int _i = 0; _i < 4; _i++) { \
            cpa16(_sb + off0 + _i * (2 * 32 * PADC), aP + _ap + _ko + (size_t)_i * 32 * RS2); \
            cpa16(_sb + TILE64B + off0 + _i * (2 * 32 * PADC), wP + _wp + _ko + (size_t)_i * 32 * RS2); \
        } \
        asm volatile("cp.async.commit_group;" ::: "memory"); \
    } while (0)

    PLOAD(0); PLOAD(1);

    const int lr = lane & 15;
    const int lh = (lane >> 4) * 8;

    float acc[4][4][4];
    #pragma unroll
    for (int i = 0; i < 4; i++)
        #pragma unroll
        for (int j = 0; j < 4; j++)
            #pragma unroll
            for (int q = 0; q < 4; q++) acc[i][j][q] = 0.f;

    const int NCHUNK = 36;
    for (int c = 0; c < NCHUNK; c++) {
        asm volatile("cp.async.wait_group 1;" ::: "memory");
        __syncthreads();
        if (c + 2 < NCHUNK) PLOAD(c + 2);
        else asm volatile("cp.async.commit_group;" ::: "memory");

        const uint32_t ab = base + (c % 3) * STGP;
        const uint32_t bb = ab + TILE64B;
        #pragma unroll
        for (int kf = 0; kf < 4; kf++) {
            uint32_t a[4][4];
            #pragma unroll
            for (int mi = 0; mi < 4; mi++)
                ldm_x4(a[mi][0], a[mi][1], a[mi][2], a[mi][3],
                       ab + 2u * ((wm * 64 + mi * 16 + lr) * PADC + kf * 16 + lh));
            uint32_t br[2][4];
            #pragma unroll
            for (int g = 0; g < 2; g++)
                ldm_x4(br[g][0], br[g][1], br[g][2], br[g][3],
                       bb + 2u * ((wn * 32 + g * 16 + lr) * PADC + kf * 16 + lh));
            #pragma unroll
            for (int mi = 0; mi < 4; mi++)
                #pragma unroll
                for (int g = 0; g < 2; g++)
                    #pragma unroll
                    for (int s = 0; s < 2; s++)
                        mma_bf(acc[mi][g * 2 + s], a[mi], br[g][s], br[g][s + 2]);
        }
    }
    #undef PLOAD

    const int er = lane >> 2;
    const int ec = (lane & 3) * 2;
    #pragma unroll
    for (int mi = 0; mi < 4; mi++) {
        #pragma unroll
        for (int ni = 0; ni < 4; ni++) {
            int m = m0 + wm * 64 + mi * 16 + er;
            int cl = wn * 32 + ni * 8 + ec;
            float bx = __ldg(biasb + cl), by = __ldg(biasb + cl + 1);
            float v00 = acc[mi][ni][0] + bx, v01 = acc[mi][ni][1] + by;
            float v10 = acc[mi][ni][2] + bx, v11 = acc[mi][ni][3] + by;
            if (OUT == 2) {
                *(__half2*)(Ch + (size_t)m * E2_ + n0 + cl)       = __floats2half2_rn(v00, v01);
                *(__half2*)(Ch + (size_t)(m + 8) * E2_ + n0 + cl) = __floats2half2_rn(v10, v11);
            } else {
                *(float2*)(Cf + (size_t)m * E_ + n0 + cl)       = make_float2(v00, v01);
                *(float2*)(Cf + (size_t)(m + 8) * E_ + n0 + cl) = make_float2(v10, v11);
            }
        }
    }
}

// Fused q/k/v projections: grid (12, 64, 3).
__global__ __launch_bounds__(256, 2) void proj_qkv(
    const __nv_bfloat16* __restrict__ Osp, const __nv_bfloat16* __restrict__ Vsp,
    const __nv_bfloat16* __restrict__ Lsp,
    const __nv_bfloat16* __restrict__ w1sp, const __nv_bfloat16* __restrict__ w2sp,
    const float* __restrict__ b1, const float* __restrict__ b2,
    __half* __restrict__ qq, __half* __restrict__ kv1, __half* __restrict__ kv2)
{
    extern __shared__ char smx[];
    const int z = blockIdx.z;
    const size_t WS = (size_t)E_ * RS2;
    const __nv_bfloat16 *A, *W1, *W2;
    const float *bi1, *bi2;
    __half* out;
    if (z == 0) {
        if (blockIdx.y >= 32) return;
        A = Osp; W1 = w1sp; W2 = w2sp; bi1 = b1; bi2 = b2; out = qq;
    } else if (z == 1) {
        A = Vsp; W1 = w1sp + WS; W2 = w1sp + 2 * WS;
        bi1 = b1 + E_; bi2 = b1 + 2 * E_; out = kv1;
    } else {
        A = Lsp; W1 = w2sp + WS; W2 = w2sp + 2 * WS;
        bi1 = b2 + E_; bi2 = b2 + 2 * E_; out = kv2;
    }
    const int n0 = blockIdx.x * 128;
    const int m0 = blockIdx.y * 128;
    const __nv_bfloat16* Wb = (n0 < E_) ? W1 + (size_t)n0 * RS2
                                        : W2 + (size_t)(n0 - E_) * RS2;
    const float* biasb = (n0 < E_) ? bi1 + n0 : bi2 + (n0 - E_);
    proj_body<2>(A, Wb, biasb, nullptr, out, m0, n0, smx);
}

// Output projection: grid (6, 32), fp32 out.
__global__ __launch_bounds__(256, 2) void proj_out(
    const __nv_bfloat16* __restrict__ ctxsp, const __nv_bfloat16* __restrict__ owsp,
    const float* __restrict__ ob, float* __restrict__ out)
{
    extern __shared__ char smx[];
    const int n0 = blockIdx.x * 128;
    const int m0 = blockIdx.y * 128;
    proj_body<0>(ctxsp, owsp + (size_t)n0 * RS2, ob + n0, out, nullptr, m0, n0, smx);
}

// ---------------------------------------------------------------------------
// Scores (fp16 HMMA, K=64): S = 0.125*q·k^T + mask. grid (16, 4, 96).
// ---------------------------------------------------------------------------
__global__ __launch_bounds__(256) void scores_mma(
    const __half* __restrict__ Q, const __half* __restrict__ KV1,
    const __half* __restrict__ KV2,
    const float* __restrict__ mask, __half* __restrict__ S)
{
    __shared__ __align__(16) __half As[128 * PADC];
    __shared__ __align__(16) __half Bs[128 * PADC];

    const int tid  = threadIdx.x;
    const int warp = tid >> 5, lane = tid & 31;
    const int wm = warp >> 2, wn = warp & 3;
    const int z = blockIdx.z;
    const int b = z / H_, h = z % H_;
    const int m0 = blockIdx.y * 128;
    const int n0 = blockIdx.x * 128;
    const bool src2 = (n0 >= LV_);
    const int sr0 = src2 ? n0 - LV_ : n0;
    const __half* kv = src2 ? KV2 : KV1;
    const int qoff = (src2 ? E_ : 0) + h * D_;

    const uint32_t baseA = smem_u32(As);
    const uint32_t baseB = smem_u32(Bs);

    #pragma unroll
    for (int i = 0; i < 4; i++) {
        int idx = tid + i * 256;
        int r = idx >> 3, c = (idx & 7) * 8;
        cpa16(baseA + 2u * (r * PADC + c),
              Q + (size_t)(b * LO_ + m0 + r) * E2_ + qoff + c);
        cpa16(baseB + 2u * (r * PADC + c),
              kv + (size_t)(b * LV_ + sr0 + r) * E2_ + h * D_ + c);
    }
    asm volatile("cp.async.commit_group;" ::: "memory");
    asm volatile("cp.async.wait_group 0;" ::: "memory");
    __syncthreads();

    const int lr = lane & 15;
    const int lh = (lane >> 4) * 8;

    float acc[4][4][4];
    #pragma unroll
    for (int i = 0; i < 4; i++)
        #pragma unroll
        for (int j = 0; j < 4; j++)
            #pragma unroll
            for (int q = 0; q < 4; q++) acc[i][j][q] = 0.f;

    #pragma unroll
    for (int kf = 0; kf < 4; kf++) {
        uint32_t a[4][4];
        #pragma unroll
        for (int mi = 0; mi < 4; mi++)
            ldm_x4(a[mi][0], a[mi][1], a[mi][2], a[mi][3],
                   baseA + 2u * ((wm * 64 + mi * 16 + lr) * PADC + kf * 16 + lh));
        uint32_t br[2][4];
        #pragma unroll
        for (int g = 0; g < 2; g++)
            ldm_x4(br[g][0], br[g][1], br[g][2], br[g][3],
                   baseB + 2u * ((wn * 32 + g * 16 + lr) * PADC + kf * 16 + lh));
        #pragma unroll
        for (int mi = 0; mi < 4; mi++)
            #pragma unroll
            for (int g = 0; g < 2; g++)
                #pragma unroll
                for (int s = 0; s < 2; s++)
                    mma_hf(acc[mi][g * 2 + s], a[mi], br[g][s], br[g][s + 2]);
    }

    const int er = lane >> 2;
    const int ec = (lane & 3) * 2;
    #pragma unroll
    for (int mi = 0; mi < 4; mi++) {
        #pragma unroll
        for (int ni = 0; ni < 4; ni++) {
            int m = m0 + wm * 64 + mi * 16 + er;
            int n = n0 + wn * 32 + ni * 8 + ec;
            float2 mk0 = *(const float2*)(mask + (size_t)m * LS_ + n);
            float2 mk1 = *(const float2*)(mask + (size_t)(m + 8) * LS_ + n);
            *(__half2*)(S + ((size_t)z * LO_ + m) * LS_ + n) =
                __floats2half2_rn(acc[mi][ni][0] * 0.125f + mk0.x,
                                  acc[mi][ni][1] * 0.125f + mk0.y);
            *(__half2*)(S + ((size_t)z * LO_ + m + 8) * LS_ + n) =
                __floats2half2_rn(acc[mi][ni][2] * 0.125f + mk1.x,
                                  acc[mi][ni][3] * 0.125f + mk1.y);
        }
    }
}

// ---------------------------------------------------------------------------
// Softmax v2: register-resident, 512 threads, 4 elems/thread.
// ---------------------------------------------------------------------------
__global__ __launch_bounds__(512) void softmax_kernel(
    const __half* __restrict__ S, __half* __restrict__ P,
    float* __restrict__ avg_out)
{
    __shared__ float red[16];
    const int bt = blockIdx.x;
    const int b = bt / LO_, t = bt % LO_;
    const int tid = threadIdx.x;
    const int lane = tid & 31, wid = tid >> 5;

    float av[4] = {0.f, 0.f, 0.f, 0.f};

    for (int h = 0; h < H_; h++) {
        const __half2* Sr = (const __half2*)(S + (((size_t)(b * H_ + h)) * LO_ + t) * LS_);
        __half2* Pr = (__half2*)(P + (((size_t)(b * H_ + h)) * LO_ + t) * LS_);

        float2 u = __half22float2(Sr[tid]);
        float2 w = __half22float2(Sr[tid + 512]);

        float lmax = fmaxf(fmaxf(u.x, u.y), fmaxf(w.x, w.y));
        #pragma unroll
        for (int o = 16; o; o >>= 1) lmax = fmaxf(lmax, __shfl_xor_sync(~0u, lmax, o));
        if (lane == 0) red[wid] = lmax;
        __syncthreads();
        float m = red[0];
        #pragma unroll
        for (int i = 1; i < 16; i++) m = fmaxf(m, red[i]);

        float e0 = __expf(u.x - m), e1 = __expf(u.y - m);
        float e2 = __expf(w.x - m), e3 = __expf(w.y - m);
        float lsum = (e0 + e1) + (e2 + e3);
        #pragma unroll
        for (int o = 16; o; o >>= 1) lsum += __shfl_xor_sync(~0u, lsum, o);
        __syncthreads();                 // all reads of red done
        if (lane == 0) red[wid] = lsum;
        __syncthreads();
        float ssum = 0.f;
        #pragma unroll
        for (int i = 0; i < 16; i++) ssum += red[i];
        float inv = 1.f / ssum;

        float p0 = e0 * inv, p1 = e1 * inv, p2 = e2 * inv, p3 = e3 * inv;
        Pr[tid]       = __floats2half2_rn(p0, p1);
        Pr[tid + 512] = __floats2half2_rn(p2, p3);
        av[0] += p0 * (1.f / H_); av[1] += p1 * (1.f / H_);
        av[2] += p2 * (1.f / H_); av[3] += p3 * (1.f / H_);
        __syncthreads();                 // protect red for next head
    }

    float2* A2 = (float2*)(avg_out + (size_t)bt * LS_);
    A2[tid]       = make_float2(av[0], av[1]);
    A2[tid + 512] = make_float2(av[2], av[3]);
}

// ---------------------------------------------------------------------------
// Context (fp16 HMMA, K=2048, K-chunk 64, 3 stages): grid (1, 4, 96).
// ---------------------------------------------------------------------------
__global__ __launch_bounds__(256, 2) void ctx_mma(
    const __half* __restrict__ P,
    const __half* __restrict__ KV1, const __half* __restrict__ KV2,
    __nv_bfloat16* __restrict__ Cs)
{
    extern __shared__ char smx[];
    const uint32_t base = smem_u32(smx);

    const int tid  = threadIdx.x;
    const int warp = tid >> 5, lane = tid & 31;
    const int wm = warp >> 2, wn = warp & 3;
    const int z = blockIdx.z;
    const int b = z / H_, h = z % H_;
    const int m0 = blockIdx.y * 128;

    const int rA = tid >> 3;            // 0..31
    const int c8 = (tid & 7) * 8;
    const __half* aP = P + ((size_t)z * LO_ + m0 + rA) * LS_ + c8;
    const uint32_t off0 = 2u * (rA * PADC + c8);
    const __half* v1b = KV1 + (size_t)b * LV_ * E2_ + E_ + h * D_ + c8;
    const __half* v2b = KV2 + (size_t)b * LL_ * E2_ + E_ + h * D_ + c8;

    #define CLOAD(j) do { \
        int _ko = (j) * 64; \
        uint32_t _sb = base + ((j) % 3) * STGC; \
        _Pragma("unroll") \
        for (int _i = 0; _i < 4; _i++) \
            cpa16(_sb + off0 + _i * (2 * 32 * PADC), aP + _ko + (size_t)_i * 32 * LS_); \
        _Pragma("unroll") \
        for (int _i = 0; _i < 2; _i++) { \
            int _s = _ko + rA + 32 * _i; \
            const __half* _src = (_s < LV_) ? v1b + (size_t)_s * E2_ \
                                            : v2b + (size_t)(_s - LV_) * E2_; \
            cpa16(_sb + TILE64B + off0 + _i * (2 * 32 * PADC), _src); \
        } \
        asm volatile("cp.async.commit_group;" ::: "memory"); \
    } while (0)

    CLOAD(0); CLOAD(1);

    const int lr = lane & 15;
    const int lh = (lane >> 4) * 8;
    const int tg  = lane >> 3;
    const int tlr = lane & 7;
    const int tko = (tg & 1) * 8;
    const int tno = (tg >> 1) * 8;

    float acc[4][2][4];
    #pragma unroll
    for (int i = 0; i < 4; i++)
        #pragma unroll
        for (int j = 0; j < 2; j++)
            #pragma unroll
            for (int q = 0; q < 4; q++) acc[i][j][q] = 0.f;

    const int NCHUNK = 32;
    for (int c = 0; c < NCHUNK; c++) {
        asm volatile("cp.async.wait_group 1;" ::: "memory");
        __syncthreads();
        if (c + 2 < NCHUNK) CLOAD(c + 2);
        else asm volatile("cp.async.commit_group;" ::: "memory");

        const uint32_t ab = base + (c % 3) * STGC;
        const uint32_t bb = ab + TILE64B;
        #pragma unroll
        for (int kf = 0; kf < 4; kf++) {
            uint32_t a[4][4];
            #pragma unroll
            for (int mi = 0; mi < 4; mi++)
                ldm_x4(a[mi][0], a[mi][1], a[mi][2], a[mi][3],
                       ab + 2u * ((wm * 64 + mi * 16 + lr) * PADC + kf * 16 + lh));
            uint32_t rb[4];
            ldm_x4_t(rb[0], rb[1], rb[2], rb[3],
                     bb + 2u * ((kf * 16 + tko + tlr) * PADC + wn * 16 + tno));
            #pragma unroll
            for (int mi = 0; mi < 4; mi++)
                #pragma unroll
                for (int nb = 0; nb < 2; nb++)
                    mma_hf(acc[mi][nb], a[mi], rb[nb * 2], rb[nb * 2 + 1]);
        }
    }
    #undef CLOAD

    const int er = lane >> 2;
    const int ec = (lane & 3) * 2;
    #pragma unroll
    for (int mi = 0; mi < 4; mi++) {
        #pragma unroll
        for (int nb = 0; nb < 2; nb++) {
            int m = m0 + wm * 64 + mi * 16 + er;
            int nl = wn * 16 + nb * 8 + ec;
            __nv_bfloat16* d0 = Cs + (size_t)(b * LO_ + m) * RS2 + h * D_ + nl;
            __nv_bfloat16* d1 = Cs + (size_t)(b * LO_ + m + 8) * RS2 + h * D_ + nl;
            __nv_bfloat16 h0, l0, h1, l1;
            fsplit(acc[mi][nb][0], h0, l0); fsplit(acc[mi][nb][1], h1, l1);
            *(__nv_bfloat162*)(d0)      = __nv_bfloat162(h0, h1);
            *(__nv_bfloat162*)(d0 + E_) = __nv_bfloat162(l0, l1);
            fsplit(acc[mi][nb][2], h0, l0); fsplit(acc[mi][nb][3], h1, l1);
            *(__nv_bfloat162*)(d1)      = __nv_bfloat162(h0, h1);
            *(__nv_bfloat162*)(d1 + E_) = __nv_bfloat162(l0, l1);
        }
    }
}

// ---------------------------------------------------------------------------
// Launch
// ---------------------------------------------------------------------------
extern "C" void kernel_launch(void* const* d_in, const int* in_sizes, int n_in,
                              void* d_out, int out_size)
{
    (void)in_sizes; (void)n_in; (void)out_size;

    const float* V    = (const float*)d_in[0];
    const float* L    = (const float*)d_in[1];
    const float* O    = (const float*)d_in[2];
    const float* mask = (const float*)d_in[3];
    const float* w1   = (const float*)d_in[4];
    const float* b1   = (const float*)d_in[5];
    const float* w2   = (const float*)d_in[6];
    const float* b2   = (const float*)d_in[7];
    const float* ow   = (const float*)d_in[8];
    const float* ob   = (const float*)d_in[9];

    float* out = (float*)d_out;
    float* avg = out + (size_t)B_ * LO_ * E_;

    __nv_bfloat16 *Osp, *Vsp, *Lsp, *ctxsp, *w1sp, *w2sp, *owsp;
    __half *qq, *kv1, *kv2, *Sh, *Ph;
    cudaGetSymbolAddress((void**)&Osp,   g_Osp);
    cudaGetSymbolAddress((void**)&Vsp,   g_Vsp);
    cudaGetSymbolAddress((void**)&Lsp,   g_Lsp);
    cudaGetSymbolAddress((void**)&ctxsp, g_ctxsp);
    cudaGetSymbolAddress((void**)&w1sp,  g_w1sp);
    cudaGetSymbolAddress((void**)&w2sp,  g_w2sp);
    cudaGetSymbolAddress((void**)&owsp,  g_owsp);
    cudaGetSymbolAddress((void**)&qq,    g_qq);
    cudaGetSymbolAddress((void**)&kv1,   g_kv1);
    cudaGetSymbolAddress((void**)&kv2,   g_kv2);
    cudaGetSymbolAddress((void**)&Sh,    g_Sh);
    cudaGetSymbolAddress((void**)&Ph,    g_Ph);

    cudaFuncSetAttribute(proj_qkv, cudaFuncAttributeMaxDynamicSharedMemorySize, SMEM_PROJ);
    cudaFuncSetAttribute(proj_out, cudaFuncAttributeMaxDynamicSharedMemorySize, SMEM_PROJ);
    cudaFuncSetAttribute(ctx_mma,  cudaFuncAttributeMaxDynamicSharedMemorySize, SMEM_CTX);

    // 1) Fused splits
    split_all<<<(ROW * (E_ / 4)) / 256, 256>>>(V, L, O, w1, w2, ow,
                                               Vsp, Lsp, Osp, w1sp, w2sp, owsp);

    // 2) Fused q/k/v projections (one launch, grid.z selects target)
    dim3 gP(E2_ / 128, (B_ * LV_) / 128, 3);   // 12 x 64 x 3
    proj_qkv<<<gP, 256, SMEM_PROJ>>>(Osp, Vsp, Lsp, w1sp, w2sp, b1, b2, qq, kv1, kv2);

    // 3) Scores
    dim3 gS(LS_ / 128, LO_ / 128, Z_);
    scores_mma<<<gS, 256>>>(qq, kv1, kv2, mask, Sh);

    // 4) Softmax + head-average
    softmax_kernel<<<B_ * LO_, 512>>>(Sh, Ph, avg);

    // 5) Context -> bf16 split ctx
    dim3 gC(1, LO_ / 128, Z_);
    ctx_mma<<<gC, 256, SMEM_CTX>>>(Ph, kv1, kv2, ctxsp);

    // 6) Output projection
    dim3 gO(E_ / 128, (B_ * LO_) / 128);
    proj_out<<<gO, 256, SMEM_PROJ>>>(ctxsp, owsp, ob, out);
}

// round 7
// speedup vs baseline: 3.5795x; 1.2947x over previous
#include <cuda_runtime.h>
#include <cuda_bf16.h>
#include <cuda_fp16.h>
#include <math.h>
#include <stdint.h>

// Problem dims
#define E_  768
#define H_  12
#define D_  64
#define B_  8
#define LO_ 512
#define LV_ 1024
#define LL_ 1024
#define LS_ 2048
#define Z_  (B_ * H_)     // 96
#define E2_ 1536

#define PADC 72                          // padded row stride for 64-wide chunks
#define TILE64B (128 * PADC * 2)         // 18432 B: one 128x64 tile
#define STGP (2 * TILE64B)               // stage: A + B = 36864
#define SMEM_PROJ (3 * STGP)             // 110592
#define CTXB (64 * PADC * 2)
#define STGC (TILE64B + CTXB)            // 27648
#define SMEM_CTX (3 * STGC)              // 82944
#define RS2 (2 * E_)                     // 2-plane row stride (elems)

// ---------------------------------------------------------------------------
// Scratch
// ---------------------------------------------------------------------------
__device__ __half g_Osp [(size_t)B_ * LO_ * RS2];   // fp16 hi/lo planes
__device__ __half g_Vsp [(size_t)B_ * LV_ * RS2];
__device__ __half g_Lsp [(size_t)B_ * LL_ * RS2];
__device__ __half g_w1h [(size_t)(3 * E_) * E_];    // fp16 single plane
__device__ __half g_w2h [(size_t)(3 * E_) * E_];
__device__ __nv_bfloat16 g_ctxsp[(size_t)B_ * LO_ * RS2];  // bf16 hi/lo
__device__ __nv_bfloat16 g_owsp [(size_t)E_ * RS2];        // bf16 hi/lo

__device__ __half g_qq [(size_t)B_ * LO_ * E2_];   // [q1 | q2]
__device__ __half g_kv1[(size_t)B_ * LV_ * E2_];   // [k1 | v1]
__device__ __half g_kv2[(size_t)B_ * LL_ * E2_];   // [k2 | v2]
__device__ __half g_Eh [(size_t)Z_ * LO_ * LS_];   // exp(scores), unnormalized
__device__ float  g_inv[(size_t)Z_ * LO_];         // 1 / rowsum

// ---------------------------------------------------------------------------
// Helpers
// ---------------------------------------------------------------------------
__device__ __forceinline__ uint32_t smem_u32(const void* p) {
    uint32_t a;
    asm("{ .reg .u64 t; cvta.to.shared.u64 t, %1; cvt.u32.u64 %0, t; }"
        : "=r"(a) : "l"(p));
    return a;
}
__device__ __forceinline__ void cpa16(uint32_t s, const void* g) {
    asm volatile("cp.async.cg.shared.global [%0], [%1], 16;" :: "r"(s), "l"(g));
}
__device__ __forceinline__ void ldm_x4(uint32_t& r0, uint32_t& r1, uint32_t& r2,
                                       uint32_t& r3, uint32_t addr) {
    asm volatile("ldmatrix.sync.aligned.m8n8.x4.shared.b16 {%0,%1,%2,%3}, [%4];"
        : "=r"(r0), "=r"(r1), "=r"(r2), "=r"(r3) : "r"(addr));
}
__device__ __forceinline__ void ldm_x4_t(uint32_t& r0, uint32_t& r1, uint32_t& r2,
                                         uint32_t& r3, uint32_t addr) {
    asm volatile("ldmatrix.sync.aligned.m8n8.x4.trans.shared.b16 {%0,%1,%2,%3}, [%4];"
        : "=r"(r0), "=r"(r1), "=r"(r2), "=r"(r3) : "r"(addr));
}
__device__ __forceinline__ void mma_bf(float* d, const uint32_t* a,
                                       uint32_t b0, uint32_t b1) {
    asm volatile(
        "mma.sync.aligned.m16n8k16.row.col.f32.bf16.bf16.f32 "
        "{%0,%1,%2,%3}, {%4,%5,%6,%7}, {%8,%9}, {%0,%1,%2,%3};"
        : "+f"(d[0]), "+f"(d[1]), "+f"(d[2]), "+f"(d[3])
        : "r"(a[0]), "r"(a[1]), "r"(a[2]), "r"(a[3]), "r"(b0), "r"(b1));
}
__device__ __forceinline__ void mma_hf(float* d, const uint32_t* a,
                                       uint32_t b0, uint32_t b1) {
    asm volatile(
        "mma.sync.aligned.m16n8k16.row.col.f32.f16.f16.f32 "
        "{%0,%1,%2,%3}, {%4,%5,%6,%7}, {%8,%9}, {%0,%1,%2,%3};"
        : "+f"(d[0]), "+f"(d[1]), "+f"(d[2]), "+f"(d[3])
        : "r"(a[0]), "r"(a[1]), "r"(a[2]), "r"(a[3]), "r"(b0), "r"(b1));
}
__device__ __forceinline__ void fsplit_bf(float x, __nv_bfloat16& h, __nv_bfloat16& l) {
    h = __float2bfloat16(x);
    l = __float2bfloat16(x - __bfloat162float(h));
}

// ---------------------------------------------------------------------------
// Fused split. Rows 0..RO: activations -> fp16 hi/lo planes.
// RO..RW2: weights -> fp16 single plane. RW2..ROW: ow -> bf16 hi/lo planes.
// ---------------------------------------------------------------------------
#define RV 8192
#define RL 16384
#define RO 20480
#define RW1 22784
#define RW2 25088
#define ROW 25856
__global__ __launch_bounds__(256) void split_all(
    const float* __restrict__ V, const float* __restrict__ L,
    const float* __restrict__ O, const float* __restrict__ w1,
    const float* __restrict__ w2, const float* __restrict__ ow,
    __half* __restrict__ Vsp, __half* __restrict__ Lsp,
    __half* __restrict__ Osp, __half* __restrict__ w1h,
    __half* __restrict__ w2h, __nv_bfloat16* __restrict__ owsp)
{
    const int CP = E_ / 4;
    int gid = blockIdx.x * 256 + threadIdx.x;
    int r = gid / CP, c4 = (gid % CP) * 4;
    int mode;            // 0 = fp16 2-plane, 1 = fp16 1-plane, 2 = bf16 2-plane
    const float* x;
    void* y;
    if      (r < RV)  { x = V;  y = Vsp;  mode = 0; }
    else if (r < RL)  { x = L;  y = Lsp;  mode = 0; r -= RV; }
    else if (r < RO)  { x = O;  y = Osp;  mode = 0; r -= RL; }
    else if (r < RW1) { x = w1; y = w1h;  mode = 1; r -= RO; }
    else if (r < RW2) { x = w2; y = w2h;  mode = 1; r -= RW1; }
    else if (r < ROW) { x = ow; y = owsp; mode = 2; r -= RW2; }
    else return;
    float4 v = *(const float4*)(x + (size_t)r * E_ + c4);
    float vv[4] = {v.x, v.y, v.z, v.w};
    if (mode == 1) {
        uint64_t hp = 0;
        #pragma unroll
        for (int i = 0; i < 4; i++)
            hp |= (uint64_t)__half_as_ushort(__float2half_rn(vv[i])) << (16 * i);
        *(uint64_t*)((__half*)y + (size_t)r * E_ + c4) = hp;
    } else if (mode == 0) {
        uint64_t hp = 0, lp = 0;
        #pragma unroll
        for (int i = 0; i < 4; i++) {
            __half hi = __float2half_rn(vv[i]);
            __half lo = __float2half_rn(vv[i] - __half2float(hi));
            hp |= (uint64_t)__half_as_ushort(hi) << (16 * i);
            lp |= (uint64_t)__half_as_ushort(lo) << (16 * i);
        }
        __half* row = (__half*)y + (size_t)r * RS2 + c4;
        *(uint64_t*)(row)      = hp;
        *(uint64_t*)(row + E_) = lp;
    } else {
        uint64_t hp = 0, lp = 0;
        #pragma unroll
        for (int i = 0; i < 4; i++) {
            __nv_bfloat16 hi, lo;
            fsplit_bf(vv[i], hi, lo);
            hp |= (uint64_t)__bfloat16_as_ushort(hi) << (16 * i);
            lp |= (uint64_t)__bfloat16_as_ushort(lo) << (16 * i);
        }
        __nv_bfloat16* row = (__nv_bfloat16*)y + (size_t)r * RS2 + c4;
        *(uint64_t*)(row)      = hp;
        *(uint64_t*)(row + E_) = lp;
    }
}

// ---------------------------------------------------------------------------
// q/k/v projections (fp16 2-term: A = [hi|lo] planes, W = 1 plane, K'=1536).
// grid (12, 64, 3); fp16 out (ldc=E2_).
// ---------------------------------------------------------------------------
__global__ __launch_bounds__(256, 2) void proj_qkv(
    const __half* __restrict__ Osp, const __half* __restrict__ Vsp,
    const __half* __restrict__ Lsp,
    const __half* __restrict__ w1h, const __half* __restrict__ w2h,
    const float* __restrict__ b1, const float* __restrict__ b2,
    __half* __restrict__ qq, __half* __restrict__ kv1, __half* __restrict__ kv2)
{
    extern __shared__ char smx[];
    const uint32_t base = smem_u32(smx);
    const int z = blockIdx.z;
    const size_t WS = (size_t)E_ * E_;
    const __half *A, *W1, *W2;
    const float *bi1, *bi2;
    __half* out;
    if (z == 0) {
        if (blockIdx.y >= 32) return;
        A = Osp; W1 = w1h; W2 = w2h; bi1 = b1; bi2 = b2; out = qq;
    } else if (z == 1) {
        A = Vsp; W1 = w1h + WS; W2 = w1h + 2 * WS;
        bi1 = b1 + E_; bi2 = b1 + 2 * E_; out = kv1;
    } else {
        A = Lsp; W1 = w2h + WS; W2 = w2h + 2 * WS;
        bi1 = b2 + E_; bi2 = b2 + 2 * E_; out = kv2;
    }
    const int n0 = blockIdx.x * 128;
    const int m0 = blockIdx.y * 128;
    const __half* Wb = (n0 < E_) ? W1 + (size_t)n0 * E_
                                 : W2 + (size_t)(n0 - E_) * E_;
    const float* biasb = (n0 < E_) ? bi1 + n0 : bi2 + (n0 - E_);

    const int tid  = threadIdx.x;
    const int warp = tid >> 5, lane = tid & 31;
    const int wm = warp >> 2, wn = warp & 3;

    const int rA = tid >> 3;
    const int c8 = (tid & 7) * 8;
    const __half* aP = A + (size_t)(m0 + rA) * RS2 + c8;
    const __half* wP = Wb + (size_t)rA * E_ + c8;
    const uint32_t off0 = 2u * (rA * PADC + c8);

    #define PLOADH(j) do { \
        int _t = (j) / 12, _ko = ((j) % 12) * 64; \
        int _ap = _t * E_; \
        uint32_t _sb = base + ((j) % 3) * STGP; \
        _Pragma("unroll") \
        for (int _i = 0; _i < 4; _i++) { \
            cpa16(_sb + off0 + _i * (2 * 32 * PADC), aP + _ap + _ko + (size_t)_i * 32 * RS2); \
            cpa16(_sb + TILE64B + off0 + _i * (2 * 32 * PADC), wP + _ko + (size_t)_i * 32 * E_); \
        } \
        asm volatile("cp.async.commit_group;" ::: "memory"); \
    } while (0)

    PLOADH(0); PLOADH(1);

    const int lr = lane & 15;
    const int lh = (lane >> 4) * 8;

    float acc[4][4][4];
    #pragma unroll
    for (int i = 0; i < 4; i++)
        #pragma unroll
        for (int j = 0; j < 4; j++)
            #pragma unroll
            for (int q = 0; q < 4; q++) acc[i][j][q] = 0.f;

    const int NCHUNK = 24;
    for (int c = 0; c < NCHUNK; c++) {
        asm volatile("cp.async.wait_group 1;" ::: "memory");
        __syncthreads();
        if (c + 2 < NCHUNK) PLOADH(c + 2);
        else asm volatile("cp.async.commit_group;" ::: "memory");

        const uint32_t ab = base + (c % 3) * STGP;
        const uint32_t bb = ab + TILE64B;
        #pragma unroll
        for (int kf = 0; kf < 4; kf++) {
            uint32_t a[4][4];
            #pragma unroll
            for (int mi = 0; mi < 4; mi++)
                ldm_x4(a[mi][0], a[mi][1], a[mi][2], a[mi][3],
                       ab + 2u * ((wm * 64 + mi * 16 + lr) * PADC + kf * 16 + lh));
            uint32_t br[2][4];
            #pragma unroll
            for (int g = 0; g < 2; g++)
                ldm_x4(br[g][0], br[g][1], br[g][2], br[g][3],
                       bb + 2u * ((wn * 32 + g * 16 + lr) * PADC + kf * 16 + lh));
            #pragma unroll
            for (int mi = 0; mi < 4; mi++)
                #pragma unroll
                for (int g = 0; g < 2; g++)
                    #pragma unroll
                    for (int s = 0; s < 2; s++)
                        mma_hf(acc[mi][g * 2 + s], a[mi], br[g][s], br[g][s + 2]);
        }
    }
    #undef PLOADH

    const int er = lane >> 2;
    const int ec = (lane & 3) * 2;
    #pragma unroll
    for (int mi = 0; mi < 4; mi++) {
        #pragma unroll
        for (int ni = 0; ni < 4; ni++) {
            int m = m0 + wm * 64 + mi * 16 + er;
            int cl = wn * 32 + ni * 8 + ec;
            float bx = __ldg(biasb + cl), by = __ldg(biasb + cl + 1);
            *(__half2*)(out + (size_t)m * E2_ + n0 + cl) =
                __floats2half2_rn(acc[mi][ni][0] + bx, acc[mi][ni][1] + by);
            *(__half2*)(out + (size_t)(m + 8) * E2_ + n0 + cl) =
                __floats2half2_rn(acc[mi][ni][2] + bx, acc[mi][ni][3] + by);
        }
    }
}

// ---------------------------------------------------------------------------
// Output projection (bf16 3-term, K'=2304): fp32 out. grid (6, 32).
// ---------------------------------------------------------------------------
__global__ __launch_bounds__(256, 2) void proj_out(
    const __nv_bfloat16* __restrict__ A,
    const __nv_bfloat16* __restrict__ W,
    const float* __restrict__ ob, float* __restrict__ out)
{
    extern __shared__ char smx[];
    const uint32_t base = smem_u32(smx);
    const int n0 = blockIdx.x * 128;
    const int m0 = blockIdx.y * 128;
    const __nv_bfloat16* Wb = W + (size_t)n0 * RS2;
    const float* biasb = ob + n0;

    const int tid  = threadIdx.x;
    const int warp = tid >> 5, lane = tid & 31;
    const int wm = warp >> 2, wn = warp & 3;

    const int rA = tid >> 3;
    const int c8 = (tid & 7) * 8;
    const __nv_bfloat16* aP = A + (size_t)(m0 + rA) * RS2 + c8;
    const __nv_bfloat16* wP = Wb + (size_t)rA * RS2 + c8;
    const uint32_t off0 = 2u * (rA * PADC + c8);

    #define PLOAD(j) do { \
        int _t = (j) / 12, _ko = ((j) % 12) * 64; \
        int _ap = (_t == 1) ? E_ : 0, _wp = (_t == 2) ? E_ : 0; \
        uint32_t _sb = base + ((j) % 3) * STGP; \
        _Pragma("unroll") \
        for (int _i = 0; _i < 4; _i++) { \
            cpa16(_sb + off0 + _i * (2 * 32 * PADC), aP + _ap + _ko + (size_t)_i * 32 * RS2); \
            cpa16(_sb + TILE64B + off0 + _i * (2 * 32 * PADC), wP + _wp + _ko + (size_t)_i * 32 * RS2); \
        } \
        asm volatile("cp.async.commit_group;" ::: "memory"); \
    } while (0)

    PLOAD(0); PLOAD(1);

    const int lr = lane & 15;
    const int lh = (lane >> 4) * 8;

    float acc[4][4][4];
    #pragma unroll
    for (int i = 0; i < 4; i++)
        #pragma unroll
        for (int j = 0; j < 4; j++)
            #pragma unroll
            for (int q = 0; q < 4; q++) acc[i][j][q] = 0.f;

    const int NCHUNK = 36;
    for (int c = 0; c < NCHUNK; c++) {
        asm volatile("cp.async.wait_group 1;" ::: "memory");
        __syncthreads();
        if (c + 2 < NCHUNK) PLOAD(c + 2);
        else asm volatile("cp.async.commit_group;" ::: "memory");

        const uint32_t ab = base + (c % 3) * STGP;
        const uint32_t bb = ab + TILE64B;
        #pragma unroll
        for (int kf = 0; kf < 4; kf++) {
            uint32_t a[4][4];
            #pragma unroll
            for (int mi = 0; mi < 4; mi++)
                ldm_x4(a[mi][0], a[mi][1], a[mi][2], a[mi][3],
                       ab + 2u * ((wm * 64 + mi * 16 + lr) * PADC + kf * 16 + lh));
            uint32_t br[2][4];
            #pragma unroll
            for (int g = 0; g < 2; g++)
                ldm_x4(br[g][0], br[g][1], br[g][2], br[g][3],
                       bb + 2u * ((wn * 32 + g * 16 + lr) * PADC + kf * 16 + lh));
            #pragma unroll
            for (int mi = 0; mi < 4; mi++)
                #pragma unroll
                for (int g = 0; g < 2; g++)
                    #pragma unroll
                    for (int s = 0; s < 2; s++)
                        mma_bf(acc[mi][g * 2 + s], a[mi], br[g][s], br[g][s + 2]);
        }
    }
    #undef PLOAD

    const int er = lane >> 2;
    const int ec = (lane & 3) * 2;
    #pragma unroll
    for (int mi = 0; mi < 4; mi++) {
        #pragma unroll
        for (int ni = 0; ni < 4; ni++) {
            int m = m0 + wm * 64 + mi * 16 + er;
            int cl = wn * 32 + ni * 8 + ec;
            float bx = __ldg(biasb + cl), by = __ldg(biasb + cl + 1);
            *(float2*)(out + (size_t)m * E_ + n0 + cl) =
                make_float2(acc[mi][ni][0] + bx, acc[mi][ni][1] + by);
            *(float2*)(out + (size_t)(m + 8) * E_ + n0 + cl) =
                make_float2(acc[mi][ni][2] + bx, acc[mi][ni][3] + by);
        }
    }
}

// ---------------------------------------------------------------------------
// Scores (fp16, K=64): E = exp(0.125*q·k^T + mask), fp16. grid (16, 4, 96).
// ---------------------------------------------------------------------------
__global__ __launch_bounds__(256) void scores_mma(
    const __half* __restrict__ Q, const __half* __restrict__ KV1,
    const __half* __restrict__ KV2,
    const float* __restrict__ mask, __half* __restrict__ Eo)
{
    __shared__ __align__(16) __half As[128 * PADC];
    __shared__ __align__(16) __half Bs[128 * PADC];

    const int tid  = threadIdx.x;
    const int warp = tid >> 5, lane = tid & 31;
    const int wm = warp >> 2, wn = warp & 3;
    const int z = blockIdx.z;
    const int b = z / H_, h = z % H_;
    const int m0 = blockIdx.y * 128;
    const int n0 = blockIdx.x * 128;
    const bool src2 = (n0 >= LV_);
    const int sr0 = src2 ? n0 - LV_ : n0;
    const __half* kv = src2 ? KV2 : KV1;
    const int qoff = (src2 ? E_ : 0) + h * D_;

    const uint32_t baseA = smem_u32(As);
    const uint32_t baseB = smem_u32(Bs);

    #pragma unroll
    for (int i = 0; i < 4; i++) {
        int idx = tid + i * 256;
        int r = idx >> 3, c = (idx & 7) * 8;
        cpa16(baseA + 2u * (r * PADC + c),
              Q + (size_t)(b * LO_ + m0 + r) * E2_ + qoff + c);
        cpa16(baseB + 2u * (r * PADC + c),
              kv + (size_t)(b * LV_ + sr0 + r) * E2_ + h * D_ + c);
    }
    asm volatile("cp.async.commit_group;" ::: "memory");
    asm volatile("cp.async.wait_group 0;" ::: "memory");
    __syncthreads();

    const int lr = lane & 15;
    const int lh = (lane >> 4) * 8;

    float acc[4][4][4];
    #pragma unroll
    for (int i = 0; i < 4; i++)
        #pragma unroll
        for (int j = 0; j < 4; j++)
            #pragma unroll
            for (int q = 0; q < 4; q++) acc[i][j][q] = 0.f;

    #pragma unroll
    for (int kf = 0; kf < 4; kf++) {
        uint32_t a[4][4];
        #pragma unroll
        for (int mi = 0; mi < 4; mi++)
            ldm_x4(a[mi][0], a[mi][1], a[mi][2], a[mi][3],
                   baseA + 2u * ((wm * 64 + mi * 16 + lr) * PADC + kf * 16 + lh));
        uint32_t br[2][4];
        #pragma unroll
        for (int g = 0; g < 2; g++)
            ldm_x4(br[g][0], br[g][1], br[g][2], br[g][3],
                   baseB + 2u * ((wn * 32 + g * 16 + lr) * PADC + kf * 16 + lh));
        #pragma unroll
        for (int mi = 0; mi < 4; mi++)
            #pragma unroll
            for (int g = 0; g < 2; g++)
                #pragma unroll
                for (int s = 0; s < 2; s++)
                    mma_hf(acc[mi][g * 2 + s], a[mi], br[g][s], br[g][s + 2]);
    }

    const int er = lane >> 2;
    const int ec = (lane & 3) * 2;
    #pragma unroll
    for (int mi = 0; mi < 4; mi++) {
        #pragma unroll
        for (int ni = 0; ni < 4; ni++) {
            int m = m0 + wm * 64 + mi * 16 + er;
            int n = n0 + wn * 32 + ni * 8 + ec;
            float2 mk0 = *(const float2*)(mask + (size_t)m * LS_ + n);
            float2 mk1 = *(const float2*)(mask + (size_t)(m + 8) * LS_ + n);
            float s00 = fminf(acc[mi][ni][0] * 0.125f + mk0.x, 11.f);
            float s01 = fminf(acc[mi][ni][1] * 0.125f + mk0.y, 11.f);
            float s10 = fminf(acc[mi][ni][2] * 0.125f + mk1.x, 11.f);
            float s11 = fminf(acc[mi][ni][3] * 0.125f + mk1.y, 11.f);
            *(__half2*)(Eo + ((size_t)z * LO_ + m) * LS_ + n) =
                __floats2half2_rn(__expf(s00), __expf(s01));
            *(__half2*)(Eo + ((size_t)z * LO_ + m + 8) * LS_ + n) =
                __floats2half2_rn(__expf(s10), __expf(s11));
        }
    }
}

// ---------------------------------------------------------------------------
// Rowsum: per (b,t): for each head, sum E row -> inv; accumulate avg.
// ---------------------------------------------------------------------------
__global__ __launch_bounds__(512) void rowsum_kernel(
    const __half* __restrict__ E, float* __restrict__ Inv,
    float* __restrict__ avg_out)
{
    __shared__ float red[16];
    const int bt = blockIdx.x;
    const int b = bt / LO_, t = bt % LO_;
    const int tid = threadIdx.x;
    const int lane = tid & 31, wid = tid >> 5;

    float av[4] = {0.f, 0.f, 0.f, 0.f};

    for (int h = 0; h < H_; h++) {
        const int z = b * H_ + h;
        const __half2* Er = (const __half2*)(E + ((size_t)z * LO_ + t) * LS_);
        float2 u = __half22float2(Er[tid]);
        float2 w = __half22float2(Er[tid + 512]);

        float lsum = (u.x + u.y) + (w.x + w.y);
        #pragma unroll
        for (int o = 16; o; o >>= 1) lsum += __shfl_xor_sync(~0u, lsum, o);
        if (lane == 0) red[wid] = lsum;
        __syncthreads();
        float ssum = 0.f;
        #pragma unroll
        for (int i = 0; i < 16; i++) ssum += red[i];
        float inv = 1.f / ssum;
        if (tid == 0) Inv[(size_t)z * LO_ + t] = inv;

        float s = inv * (1.f / H_);
        av[0] += u.x * s; av[1] += u.y * s;
        av[2] += w.x * s; av[3] += w.y * s;
        __syncthreads();     // red reuse next head
    }

    float2* A2 = (float2*)(avg_out + (size_t)bt * LS_);
    A2[tid]       = make_float2(av[0], av[1]);
    A2[tid + 512] = make_float2(av[2], av[3]);
}

// ---------------------------------------------------------------------------
// Context (fp16, K=2048): ctx = (E·v) * inv. grid (1, 4, 96).
// ---------------------------------------------------------------------------
__global__ __launch_bounds__(256, 2) void ctx_mma(
    const __half* __restrict__ E,
    const __half* __restrict__ KV1, const __half* __restrict__ KV2,
    const float* __restrict__ Inv,
    __nv_bfloat16* __restrict__ Cs)
{
    extern __shared__ char smx[];
    const uint32_t base = smem_u32(smx);

    const int tid  = threadIdx.x;
    const int warp = tid >> 5, lane = tid & 31;
    const int wm = warp >> 2, wn = warp & 3;
    const int z = blockIdx.z;
    const int b = z / H_, h = z % H_;
    const int m0 = blockIdx.y * 128;

    const int rA = tid >> 3;
    const int c8 = (tid & 7) * 8;
    const __half* aP = E + ((size_t)z * LO_ + m0 + rA) * LS_ + c8;
    const uint32_t off0 = 2u * (rA * PADC + c8);
    const __half* v1b = KV1 + (size_t)b * LV_ * E2_ + E_ + h * D_ + c8;
    const __half* v2b = KV2 + (size_t)b * LL_ * E2_ + E_ + h * D_ + c8;

    #define CLOAD(j) do { \
        int _ko = (j) * 64; \
        uint32_t _sb = base + ((j) % 3) * STGC; \
        _Pragma("unroll") \
        for (int _i = 0; _i < 4; _i++) \
            cpa16(_sb + off0 + _i * (2 * 32 * PADC), aP + _ko + (size_t)_i * 32 * LS_); \
        _Pragma("unroll") \
        for (int _i = 0; _i < 2; _i++) { \
            int _s = _ko + rA + 32 * _i; \
            const __half* _src = (_s < LV_) ? v1b + (size_t)_s * E2_ \
                                            : v2b + (size_t)(_s - LV_) * E2_; \
            cpa16(_sb + TILE64B + off0 + _i * (2 * 32 * PADC), _src); \
        } \
        asm volatile("cp.async.commit_group;" ::: "memory"); \
    } while (0)

    CLOAD(0); CLOAD(1);

    const int lr = lane & 15;
    const int lh = (lane >> 4) * 8;
    const int tg  = lane >> 3;
    const int tlr = lane & 7;
    const int tko = (tg & 1) * 8;
    const int tno = (tg >> 1) * 8;

    float acc[4][2][4];
    #pragma unroll
    for (int i = 0; i < 4; i++)
        #pragma unroll
        for (int j = 0; j < 2; j++)
            #pragma unroll
            for (int q = 0; q < 4; q++) acc[i][j][q] = 0.f;

    const int NCHUNK = 32;
    for (int c = 0; c < NCHUNK; c++) {
        asm volatile("cp.async.wait_group 1;" ::: "memory");
        __syncthreads();
        if (c + 2 < NCHUNK) CLOAD(c + 2);
        else asm volatile("cp.async.commit_group;" ::: "memory");

        const uint32_t ab = base + (c % 3) * STGC;
        const uint32_t bb = ab + TILE64B;
        #pragma unroll
        for (int kf = 0; kf < 4; kf++) {
            uint32_t a[4][4];
            #pragma unroll
            for (int mi = 0; mi < 4; mi++)
                ldm_x4(a[mi][0], a[mi][1], a[mi][2], a[mi][3],
                       ab + 2u * ((wm * 64 + mi * 16 + lr) * PADC + kf * 16 + lh));
            uint32_t rb[4];
            ldm_x4_t(rb[0], rb[1], rb[2], rb[3],
                     bb + 2u * ((kf * 16 + tko + tlr) * PADC + wn * 16 + tno));
            #pragma unroll
            for (int mi = 0; mi < 4; mi++)
                #pragma unroll
                for (int nb = 0; nb < 2; nb++)
                    mma_hf(acc[mi][nb], a[mi], rb[nb * 2], rb[nb * 2 + 1]);
        }
    }
    #undef CLOAD

    const int er = lane >> 2;
    const int ec = (lane & 3) * 2;
    #pragma unroll
    for (int mi = 0; mi < 4; mi++) {
        int m = m0 + wm * 64 + mi * 16 + er;
        float inv0 = __ldg(Inv + (size_t)z * LO_ + m);
        float inv1 = __ldg(Inv + (size_t)z * LO_ + m + 8);
        #pragma unroll
        for (int nb = 0; nb < 2; nb++) {
            int nl = wn * 16 + nb * 8 + ec;
            __nv_bfloat16* d0 = Cs + (size_t)(b * LO_ + m) * RS2 + h * D_ + nl;
            __nv_bfloat16* d1 = Cs + (size_t)(b * LO_ + m + 8) * RS2 + h * D_ + nl;
            __nv_bfloat16 h0, l0, h1, l1;
            fsplit_bf(acc[mi][nb][0] * inv0, h0, l0);
            fsplit_bf(acc[mi][nb][1] * inv0, h1, l1);
            *(__nv_bfloat162*)(d0)      = __nv_bfloat162(h0, h1);
            *(__nv_bfloat162*)(d0 + E_) = __nv_bfloat162(l0, l1);
            fsplit_bf(acc[mi][nb][2] * inv1, h0, l0);
            fsplit_bf(acc[mi][nb][3] * inv1, h1, l1);
            *(__nv_bfloat162*)(d1)      = __nv_bfloat162(h0, h1);
            *(__nv_bfloat162*)(d1 + E_) = __nv_bfloat162(l0, l1);
        }
    }
}

// ---------------------------------------------------------------------------
// Launch
// ---------------------------------------------------------------------------
extern "C" void kernel_launch(void* const* d_in, const int* in_sizes, int n_in,
                              void* d_out, int out_size)
{
    (void)in_sizes; (void)n_in; (void)out_size;

    const float* V    = (const float*)d_in[0];
    const float* L    = (const float*)d_in[1];
    const float* O    = (const float*)d_in[2];
    const float* mask = (const float*)d_in[3];
    const float* w1   = (const float*)d_in[4];
    const float* b1   = (const float*)d_in[5];
    const float* w2   = (const float*)d_in[6];
    const float* b2   = (const float*)d_in[7];
    const float* ow   = (const float*)d_in[8];
    const float* ob   = (const float*)d_in[9];

    float* out = (float*)d_out;
    float* avg = out + (size_t)B_ * LO_ * E_;

    __half *Osp, *Vsp, *Lsp, *w1h, *w2h, *qq, *kv1, *kv2, *Eh;
    __nv_bfloat16 *ctxsp, *owsp;
    float* Inv;
    cudaGetSymbolAddress((void**)&Osp,   g_Osp);
    cudaGetSymbolAddress((void**)&Vsp,   g_Vsp);
    cudaGetSymbolAddress((void**)&Lsp,   g_Lsp);
    cudaGetSymbolAddress((void**)&w1h,   g_w1h);
    cudaGetSymbolAddress((void**)&w2h,   g_w2h);
    cudaGetSymbolAddress((void**)&ctxsp, g_ctxsp);
    cudaGetSymbolAddress((void**)&owsp,  g_owsp);
    cudaGetSymbolAddress((void**)&qq,    g_qq);
    cudaGetSymbolAddress((void**)&kv1,   g_kv1);
    cudaGetSymbolAddress((void**)&kv2,   g_kv2);
    cudaGetSymbolAddress((void**)&Eh,    g_Eh);
    cudaGetSymbolAddress((void**)&Inv,   g_inv);

    cudaFuncSetAttribute(proj_qkv, cudaFuncAttributeMaxDynamicSharedMemorySize, SMEM_PROJ);
    cudaFuncSetAttribute(proj_out, cudaFuncAttributeMaxDynamicSharedMemorySize, SMEM_PROJ);
    cudaFuncSetAttribute(ctx_mma,  cudaFuncAttributeMaxDynamicSharedMemorySize, SMEM_CTX);

    // 1) Fused splits
    split_all<<<(ROW * (E_ / 4)) / 256, 256>>>(V, L, O, w1, w2, ow,
                                               Vsp, Lsp, Osp, w1h, w2h, owsp);

    // 2) q/k/v projections (fp16 2-term, one launch)
    dim3 gP(E2_ / 128, (B_ * LV_) / 128, 3);
    proj_qkv<<<gP, 256, SMEM_PROJ>>>(Osp, Vsp, Lsp, w1h, w2h, b1, b2, qq, kv1, kv2);

    // 3) Scores -> E = exp(s)
    dim3 gS(LS_ / 128, LO_ / 128, Z_);
    scores_mma<<<gS, 256>>>(qq, kv1, kv2, mask, Eh);

    // 4) Rowsum -> inv + avg
    rowsum_kernel<<<B_ * LO_, 512>>>(Eh, Inv, avg);

    // 5) Context (normalize in epilogue) -> bf16 split ctx
    dim3 gC(1, LO_ / 128, Z_);
    ctx_mma<<<gC, 256, SMEM_CTX>>>(Eh, kv1, kv2, Inv, ctxsp);

    // 6) Output projection (bf16 3-term)
    dim3 gO(E_ / 128, (B_ * LO_) / 128);
    proj_out<<<gO, 256, SMEM_PROJ>>>(ctxsp, owsp, ob, out);
}

// round 8
// speedup vs baseline: 4.8161x; 1.3455x over previous
#include <cuda_runtime.h>
#include <cuda_bf16.h>
#include <cuda_fp16.h>
#include <math.h>
#include <stdint.h>

// Problem dims
#define E_  768
#define H_  12
#define D_  64
#define B_  8
#define LO_ 512
#define LV_ 1024
#define LL_ 1024
#define LS_ 2048
#define Z_  (B_ * H_)     // 96
#define E2_ 1536

#define PADC 72                          // padded row stride for 64-wide chunks
#define TILE64B (128 * PADC * 2)         // 18432 B: one 128x64 tile
#define STGP (2 * TILE64B)               // stage: A + B = 36864
#define SMEM_PROJ (3 * STGP)             // 110592
#define CTXB (64 * PADC * 2)
#define STGC (TILE64B + CTXB)            // 27648
#define SMEM_CTX (3 * STGC)              // 82944
#define RS2 (2 * E_)                     // 2-plane row stride (bf16 path)

// ---------------------------------------------------------------------------
// Scratch
// ---------------------------------------------------------------------------
__device__ __half g_Oh [(size_t)B_ * LO_ * E_];    // fp16 single plane
__device__ __half g_Vh [(size_t)B_ * LV_ * E_];
__device__ __half g_Lh [(size_t)B_ * LL_ * E_];
__device__ __half g_w1h[(size_t)(3 * E_) * E_];
__device__ __half g_w2h[(size_t)(3 * E_) * E_];
__device__ __nv_bfloat16 g_ctxsp[(size_t)B_ * LO_ * RS2];  // bf16 hi/lo
__device__ __nv_bfloat16 g_owsp [(size_t)E_ * RS2];        // bf16 hi/lo

__device__ __half g_qq [(size_t)B_ * LO_ * E2_];   // [q1 | q2]
__device__ __half g_kv1[(size_t)B_ * LV_ * E2_];   // [k1 | v1]
__device__ __half g_kv2[(size_t)B_ * LL_ * E2_];   // [k2 | v2]
__device__ __half g_Eh [(size_t)Z_ * LO_ * LS_];   // exp(scores), unnormalized
__device__ float  g_inv[(size_t)Z_ * LO_];         // 1 / rowsum

// ---------------------------------------------------------------------------
// Helpers
// ---------------------------------------------------------------------------
__device__ __forceinline__ uint32_t smem_u32(const void* p) {
    uint32_t a;
    asm("{ .reg .u64 t; cvta.to.shared.u64 t, %1; cvt.u32.u64 %0, t; }"
        : "=r"(a) : "l"(p));
    return a;
}
__device__ __forceinline__ void cpa16(uint32_t s, const void* g) {
    asm volatile("cp.async.cg.shared.global [%0], [%1], 16;" :: "r"(s), "l"(g));
}
__device__ __forceinline__ void ldm_x4(uint32_t& r0, uint32_t& r1, uint32_t& r2,
                                       uint32_t& r3, uint32_t addr) {
    asm volatile("ldmatrix.sync.aligned.m8n8.x4.shared.b16 {%0,%1,%2,%3}, [%4];"
        : "=r"(r0), "=r"(r1), "=r"(r2), "=r"(r3) : "r"(addr));
}
__device__ __forceinline__ void ldm_x4_t(uint32_t& r0, uint32_t& r1, uint32_t& r2,
                                         uint32_t& r3, uint32_t addr) {
    asm volatile("ldmatrix.sync.aligned.m8n8.x4.trans.shared.b16 {%0,%1,%2,%3}, [%4];"
        : "=r"(r0), "=r"(r1), "=r"(r2), "=r"(r3) : "r"(addr));
}
__device__ __forceinline__ void mma_bf(float* d, const uint32_t* a,
                                       uint32_t b0, uint32_t b1) {
    asm volatile(
        "mma.sync.aligned.m16n8k16.row.col.f32.bf16.bf16.f32 "
        "{%0,%1,%2,%3}, {%4,%5,%6,%7}, {%8,%9}, {%0,%1,%2,%3};"
        : "+f"(d[0]), "+f"(d[1]), "+f"(d[2]), "+f"(d[3])
        : "r"(a[0]), "r"(a[1]), "r"(a[2]), "r"(a[3]), "r"(b0), "r"(b1));
}
__device__ __forceinline__ void mma_hf(float* d, const uint32_t* a,
                                       uint32_t b0, uint32_t b1) {
    asm volatile(
        "mma.sync.aligned.m16n8k16.row.col.f32.f16.f16.f32 "
        "{%0,%1,%2,%3}, {%4,%5,%6,%7}, {%8,%9}, {%0,%1,%2,%3};"
        : "+f"(d[0]), "+f"(d[1]), "+f"(d[2]), "+f"(d[3])
        : "r"(a[0]), "r"(a[1]), "r"(a[2]), "r"(a[3]), "r"(b0), "r"(b1));
}
__device__ __forceinline__ void fsplit_bf(float x, __nv_bfloat16& h, __nv_bfloat16& l) {
    h = __float2bfloat16(x);
    l = __float2bfloat16(x - __bfloat162float(h));
}

// ---------------------------------------------------------------------------
// Fused split: V,L,O,w1,w2 -> fp16 single plane; ow -> bf16 hi/lo planes.
// ---------------------------------------------------------------------------
#define RV 8192
#define RL 16384
#define RO 20480
#define RW1 22784
#define RW2 25088
#define ROW 25856
__global__ __launch_bounds__(256) void split_all(
    const float* __restrict__ V, const float* __restrict__ L,
    const float* __restrict__ O, const float* __restrict__ w1,
    const float* __restrict__ w2, const float* __restrict__ ow,
    __half* __restrict__ Vh, __half* __restrict__ Lh,
    __half* __restrict__ Oh, __half* __restrict__ w1h,
    __half* __restrict__ w2h, __nv_bfloat16* __restrict__ owsp)
{
    const int CP = E_ / 4;
    int gid = blockIdx.x * 256 + threadIdx.x;
    int r = gid / CP, c4 = (gid % CP) * 4;
    int mode;            // 1 = fp16 1-plane, 2 = bf16 2-plane
    const float* x;
    void* y;
    if      (r < RV)  { x = V;  y = Vh;   mode = 1; }
    else if (r < RL)  { x = L;  y = Lh;   mode = 1; r -= RV; }
    else if (r < RO)  { x = O;  y = Oh;   mode = 1; r -= RL; }
    else if (r < RW1) { x = w1; y = w1h;  mode = 1; r -= RO; }
    else if (r < RW2) { x = w2; y = w2h;  mode = 1; r -= RW1; }
    else if (r < ROW) { x = ow; y = owsp; mode = 2; r -= RW2; }
    else return;
    float4 v = *(const float4*)(x + (size_t)r * E_ + c4);
    float vv[4] = {v.x, v.y, v.z, v.w};
    if (mode == 1) {
        uint64_t hp = 0;
        #pragma unroll
        for (int i = 0; i < 4; i++)
            hp |= (uint64_t)__half_as_ushort(__float2half_rn(vv[i])) << (16 * i);
        *(uint64_t*)((__half*)y + (size_t)r * E_ + c4) = hp;
    } else {
        uint64_t hp = 0, lp = 0;
        #pragma unroll
        for (int i = 0; i < 4; i++) {
            __nv_bfloat16 hi, lo;
            fsplit_bf(vv[i], hi, lo);
            hp |= (uint64_t)__bfloat16_as_ushort(hi) << (16 * i);
            lp |= (uint64_t)__bfloat16_as_ushort(lo) << (16 * i);
        }
        __nv_bfloat16* row = (__nv_bfloat16*)y + (size_t)r * RS2 + c4;
        *(uint64_t*)(row)      = hp;
        *(uint64_t*)(row + E_) = lp;
    }
}

// ---------------------------------------------------------------------------
// q/k/v projections (fp16 1-plane x 1-plane, K'=768, 12 chunks of 64).
// grid (12, 64, 3); fp16 out (ldc=E2_).
// ---------------------------------------------------------------------------
__global__ __launch_bounds__(256, 2) void proj_qkv(
    const __half* __restrict__ Oh, const __half* __restrict__ Vh,
    const __half* __restrict__ Lh,
    const __half* __restrict__ w1h, const __half* __restrict__ w2h,
    const float* __restrict__ b1, const float* __restrict__ b2,
    __half* __restrict__ qq, __half* __restrict__ kv1, __half* __restrict__ kv2)
{
    extern __shared__ char smx[];
    const uint32_t base = smem_u32(smx);
    const int z = blockIdx.z;
    const size_t WS = (size_t)E_ * E_;
    const __half *A, *W1, *W2;
    const float *bi1, *bi2;
    __half* out;
    if (z == 0) {
        if (blockIdx.y >= 32) return;
        A = Oh; W1 = w1h; W2 = w2h; bi1 = b1; bi2 = b2; out = qq;
    } else if (z == 1) {
        A = Vh; W1 = w1h + WS; W2 = w1h + 2 * WS;
        bi1 = b1 + E_; bi2 = b1 + 2 * E_; out = kv1;
    } else {
        A = Lh; W1 = w2h + WS; W2 = w2h + 2 * WS;
        bi1 = b2 + E_; bi2 = b2 + 2 * E_; out = kv2;
    }
    const int n0 = blockIdx.x * 128;
    const int m0 = blockIdx.y * 128;
    const __half* Wb = (n0 < E_) ? W1 + (size_t)n0 * E_
                                 : W2 + (size_t)(n0 - E_) * E_;
    const float* biasb = (n0 < E_) ? bi1 + n0 : bi2 + (n0 - E_);

    const int tid  = threadIdx.x;
    const int warp = tid >> 5, lane = tid & 31;
    const int wm = warp >> 2, wn = warp & 3;

    const int rA = tid >> 3;
    const int c8 = (tid & 7) * 8;
    const __half* aP = A + (size_t)(m0 + rA) * E_ + c8;
    const __half* wP = Wb + (size_t)rA * E_ + c8;
    const uint32_t off0 = 2u * (rA * PADC + c8);

    #define PLOADH(j) do { \
        int _ko = (j) * 64; \
        uint32_t _sb = base + ((j) % 3) * STGP; \
        _Pragma("unroll") \
        for (int _i = 0; _i < 4; _i++) { \
            cpa16(_sb + off0 + _i * (2 * 32 * PADC), aP + _ko + (size_t)_i * 32 * E_); \
            cpa16(_sb + TILE64B + off0 + _i * (2 * 32 * PADC), wP + _ko + (size_t)_i * 32 * E_); \
        } \
        asm volatile("cp.async.commit_group;" ::: "memory"); \
    } while (0)

    PLOADH(0); PLOADH(1);

    const int lr = lane & 15;
    const int lh = (lane >> 4) * 8;

    float acc[4][4][4];
    #pragma unroll
    for (int i = 0; i < 4; i++)
        #pragma unroll
        for (int j = 0; j < 4; j++)
            #pragma unroll
            for (int q = 0; q < 4; q++) acc[i][j][q] = 0.f;

    const int NCHUNK = 12;
    for (int c = 0; c < NCHUNK; c++) {
        asm volatile("cp.async.wait_group 1;" ::: "memory");
        __syncthreads();
        if (c + 2 < NCHUNK) PLOADH(c + 2);
        else asm volatile("cp.async.commit_group;" ::: "memory");

        const uint32_t ab = base + (c % 3) * STGP;
        const uint32_t bb = ab + TILE64B;
        #pragma unroll
        for (int kf = 0; kf < 4; kf++) {
            uint32_t a[4][4];
            #pragma unroll
            for (int mi = 0; mi < 4; mi++)
                ldm_x4(a[mi][0], a[mi][1], a[mi][2], a[mi][3],
                       ab + 2u * ((wm * 64 + mi * 16 + lr) * PADC + kf * 16 + lh));
            uint32_t br[2][4];
            #pragma unroll
            for (int g = 0; g < 2; g++)
                ldm_x4(br[g][0], br[g][1], br[g][2], br[g][3],
                       bb + 2u * ((wn * 32 + g * 16 + lr) * PADC + kf * 16 + lh));
            #pragma unroll
            for (int mi = 0; mi < 4; mi++)
                #pragma unroll
                for (int g = 0; g < 2; g++)
                    #pragma unroll
                    for (int s = 0; s < 2; s++)
                        mma_hf(acc[mi][g * 2 + s], a[mi], br[g][s], br[g][s + 2]);
        }
    }
    #undef PLOADH

    const int er = lane >> 2;
    const int ec = (lane & 3) * 2;
    #pragma unroll
    for (int mi = 0; mi < 4; mi++) {
        #pragma unroll
        for (int ni = 0; ni < 4; ni++) {
            int m = m0 + wm * 64 + mi * 16 + er;
            int cl = wn * 32 + ni * 8 + ec;
            float bx = __ldg(biasb + cl), by = __ldg(biasb + cl + 1);
            *(__half2*)(out + (size_t)m * E2_ + n0 + cl) =
                __floats2half2_rn(acc[mi][ni][0] + bx, acc[mi][ni][1] + by);
            *(__half2*)(out + (size_t)(m + 8) * E2_ + n0 + cl) =
                __floats2half2_rn(acc[mi][ni][2] + bx, acc[mi][ni][3] + by);
        }
    }
}

// ---------------------------------------------------------------------------
// Output projection (bf16 3-term, K'=2304): fp32 out. grid (6, 32).
// ---------------------------------------------------------------------------
__global__ __launch_bounds__(256, 2) void proj_out(
    const __nv_bfloat16* __restrict__ A,
    const __nv_bfloat16* __restrict__ W,
    const float* __restrict__ ob, float* __restrict__ out)
{
    extern __shared__ char smx[];
    const uint32_t base = smem_u32(smx);
    const int n0 = blockIdx.x * 128;
    const int m0 = blockIdx.y * 128;
    const __nv_bfloat16* Wb = W + (size_t)n0 * RS2;
    const float* biasb = ob + n0;

    const int tid  = threadIdx.x;
    const int warp = tid >> 5, lane = tid & 31;
    const int wm = warp >> 2, wn = warp & 3;

    const int rA = tid >> 3;
    const int c8 = (tid & 7) * 8;
    const __nv_bfloat16* aP = A + (size_t)(m0 + rA) * RS2 + c8;
    const __nv_bfloat16* wP = Wb + (size_t)rA * RS2 + c8;
    const uint32_t off0 = 2u * (rA * PADC + c8);

    #define PLOAD(j) do { \
        int _t = (j) / 12, _ko = ((j) % 12) * 64; \
        int _ap = (_t == 1) ? E_ : 0, _wp = (_t == 2) ? E_ : 0; \
        uint32_t _sb = base + ((j) % 3) * STGP; \
        _Pragma("unroll") \
        for (int _i = 0; _i < 4; _i++) { \
            cpa16(_sb + off0 + _i * (2 * 32 * PADC), aP + _ap + _ko + (size_t)_i * 32 * RS2); \
            cpa16(_sb + TILE64B + off0 + _i * (2 * 32 * PADC), wP + _wp + _ko + (size_t)_i * 32 * RS2); \
        } \
        asm volatile("cp.async.commit_group;" ::: "memory"); \
    } while (0)

    PLOAD(0); PLOAD(1);

    const int lr = lane & 15;
    const int lh = (lane >> 4) * 8;

    float acc[4][4][4];
    #pragma unroll
    for (int i = 0; i < 4; i++)
        #pragma unroll
        for (int j = 0; j < 4; j++)
            #pragma unroll
            for (int q = 0; q < 4; q++) acc[i][j][q] = 0.f;

    const int NCHUNK = 36;
    for (int c = 0; c < NCHUNK; c++) {
        asm volatile("cp.async.wait_group 1;" ::: "memory");
        __syncthreads();
        if (c + 2 < NCHUNK) PLOAD(c + 2);
        else asm volatile("cp.async.commit_group;" ::: "memory");

        const uint32_t ab = base + (c % 3) * STGP;
        const uint32_t bb = ab + TILE64B;
        #pragma unroll
        for (int kf = 0; kf < 4; kf++) {
            uint32_t a[4][4];
            #pragma unroll
            for (int mi = 0; mi < 4; mi++)
                ldm_x4(a[mi][0], a[mi][1], a[mi][2], a[mi][3],
                       ab + 2u * ((wm * 64 + mi * 16 + lr) * PADC + kf * 16 + lh));
            uint32_t br[2][4];
            #pragma unroll
            for (int g = 0; g < 2; g++)
                ldm_x4(br[g][0], br[g][1], br[g][2], br[g][3],
                       bb + 2u * ((wn * 32 + g * 16 + lr) * PADC + kf * 16 + lh));
            #pragma unroll
            for (int mi = 0; mi < 4; mi++)
                #pragma unroll
                for (int g = 0; g < 2; g++)
                    #pragma unroll
                    for (int s = 0; s < 2; s++)
                        mma_bf(acc[mi][g * 2 + s], a[mi], br[g][s], br[g][s + 2]);
        }
    }
    #undef PLOAD

    const int er = lane >> 2;
    const int ec = (lane & 3) * 2;
    #pragma unroll
    for (int mi = 0; mi < 4; mi++) {
        #pragma unroll
        for (int ni = 0; ni < 4; ni++) {
            int m = m0 + wm * 64 + mi * 16 + er;
            int cl = wn * 32 + ni * 8 + ec;
            float bx = __ldg(biasb + cl), by = __ldg(biasb + cl + 1);
            *(float2*)(out + (size_t)m * E_ + n0 + cl) =
                make_float2(acc[mi][ni][0] + bx, acc[mi][ni][1] + by);
            *(float2*)(out + (size_t)(m + 8) * E_ + n0 + cl) =
                make_float2(acc[mi][ni][2] + bx, acc[mi][ni][3] + by);
        }
    }
}

// ---------------------------------------------------------------------------
// Scores (fp16, K=64): E = exp(0.125*q·k^T + mask), fp16. grid (16, 4, 96).
// ---------------------------------------------------------------------------
__global__ __launch_bounds__(256) void scores_mma(
    const __half* __restrict__ Q, const __half* __restrict__ KV1,
    const __half* __restrict__ KV2,
    const float* __restrict__ mask, __half* __restrict__ Eo)
{
    __shared__ __align__(16) __half As[128 * PADC];
    __shared__ __align__(16) __half Bs[128 * PADC];

    const int tid  = threadIdx.x;
    const int warp = tid >> 5, lane = tid & 31;
    const int wm = warp >> 2, wn = warp & 3;
    const int z = blockIdx.z;
    const int b = z / H_, h = z % H_;
    const int m0 = blockIdx.y * 128;
    const int n0 = blockIdx.x * 128;
    const bool src2 = (n0 >= LV_);
    const int sr0 = src2 ? n0 - LV_ : n0;
    const __half* kv = src2 ? KV2 : KV1;
    const int qoff = (src2 ? E_ : 0) + h * D_;

    const uint32_t baseA = smem_u32(As);
    const uint32_t baseB = smem_u32(Bs);

    #pragma unroll
    for (int i = 0; i < 4; i++) {
        int idx = tid + i * 256;
        int r = idx >> 3, c = (idx & 7) * 8;
        cpa16(baseA + 2u * (r * PADC + c),
              Q + (size_t)(b * LO_ + m0 + r) * E2_ + qoff + c);
        cpa16(baseB + 2u * (r * PADC + c),
              kv + (size_t)(b * LV_ + sr0 + r) * E2_ + h * D_ + c);
    }
    asm volatile("cp.async.commit_group;" ::: "memory");
    asm volatile("cp.async.wait_group 0;" ::: "memory");
    __syncthreads();

    const int lr = lane & 15;
    const int lh = (lane >> 4) * 8;

    float acc[4][4][4];
    #pragma unroll
    for (int i = 0; i < 4; i++)
        #pragma unroll
        for (int j = 0; j < 4; j++)
            #pragma unroll
            for (int q = 0; q < 4; q++) acc[i][j][q] = 0.f;

    #pragma unroll
    for (int kf = 0; kf < 4; kf++) {
        uint32_t a[4][4];
        #pragma unroll
        for (int mi = 0; mi < 4; mi++)
            ldm_x4(a[mi][0], a[mi][1], a[mi][2], a[mi][3],
                   baseA + 2u * ((wm * 64 + mi * 16 + lr) * PADC + kf * 16 + lh));
        uint32_t br[2][4];
        #pragma unroll
        for (int g = 0; g < 2; g++)
            ldm_x4(br[g][0], br[g][1], br[g][2], br[g][3],
                   baseB + 2u * ((wn * 32 + g * 16 + lr) * PADC + kf * 16 + lh));
        #pragma unroll
        for (int mi = 0; mi < 4; mi++)
            #pragma unroll
            for (int g = 0; g < 2; g++)
                #pragma unroll
                for (int s = 0; s < 2; s++)
                    mma_hf(acc[mi][g * 2 + s], a[mi], br[g][s], br[g][s + 2]);
    }

    const int er = lane >> 2;
    const int ec = (lane & 3) * 2;
    #pragma unroll
    for (int mi = 0; mi < 4; mi++) {
        #pragma unroll
        for (int ni = 0; ni < 4; ni++) {
            int m = m0 + wm * 64 + mi * 16 + er;
            int n = n0 + wn * 32 + ni * 8 + ec;
            float2 mk0 = *(const float2*)(mask + (size_t)m * LS_ + n);
            float2 mk1 = *(const float2*)(mask + (size_t)(m + 8) * LS_ + n);
            float s00 = fminf(acc[mi][ni][0] * 0.125f + mk0.x, 11.f);
            float s01 = fminf(acc[mi][ni][1] * 0.125f + mk0.y, 11.f);
            float s10 = fminf(acc[mi][ni][2] * 0.125f + mk1.x, 11.f);
            float s11 = fminf(acc[mi][ni][3] * 0.125f + mk1.y, 11.f);
            *(__half2*)(Eo + ((size_t)z * LO_ + m) * LS_ + n) =
                __floats2half2_rn(__expf(s00), __expf(s01));
            *(__half2*)(Eo + ((size_t)z * LO_ + m + 8) * LS_ + n) =
                __floats2half2_rn(__expf(s10), __expf(s11));
        }
    }
}

// ---------------------------------------------------------------------------
// Rowsum v2: register-held E across all 12 heads, 2 syncthreads total.
// ---------------------------------------------------------------------------
__global__ __launch_bounds__(512) void rowsum_kernel(
    const __half* __restrict__ E, float* __restrict__ Inv,
    float* __restrict__ avg_out)
{
    __shared__ float sred[16 * H_];   // per-warp partials
    __shared__ float sinv[H_];

    const int bt = blockIdx.x;
    const int b = bt / LO_, t = bt % LO_;
    const int tid = threadIdx.x;
    const int lane = tid & 31, wid = tid >> 5;

    // Phase 1: load all heads' 4 elems, per-head partial sum.
    uint32_t eh[H_][2];
    float hsum[H_];
    #pragma unroll
    for (int h = 0; h < H_; h++) {
        const int z = b * H_ + h;
        const __half2* Er = (const __half2*)(E + ((size_t)z * LO_ + t) * LS_);
        __half2 a = Er[tid], c = Er[tid + 512];
        eh[h][0] = *(const uint32_t*)&a;
        eh[h][1] = *(const uint32_t*)&c;
        float2 u = __half22float2(a), w = __half22float2(c);
        hsum[h] = (u.x + u.y) + (w.x + w.y);
    }

    // Phase 2: warp reductions, write per-warp partials.
    #pragma unroll
    for (int h = 0; h < H_; h++) {
        #pragma unroll
        for (int o = 16; o; o >>= 1)
            hsum[h] += __shfl_xor_sync(~0u, hsum[h], o);
        if (lane == 0) sred[wid * H_ + h] = hsum[h];
    }
    __syncthreads();

    // Phase 3: warp w (< 12) finalizes head w's inv.
    if (wid < H_ && lane < 16) {
        float s = sred[lane * H_ + wid];
        #pragma unroll
        for (int o = 8; o; o >>= 1) s += __shfl_xor_sync(0xFFFFu, s, o);
        if (lane == 0) {
            float inv = 1.f / s;
            sinv[wid] = inv;
            Inv[(size_t)(b * H_ + wid) * LO_ + t] = inv;
        }
    }
    __syncthreads();

    // Phase 4: avg from register-held E.
    float a0 = 0.f, a1 = 0.f, a2 = 0.f, a3 = 0.f;
    #pragma unroll
    for (int h = 0; h < H_; h++) {
        float sc = sinv[h] * (1.f / H_);
        float2 u = __half22float2(*(const __half2*)&eh[h][0]);
        float2 w = __half22float2(*(const __half2*)&eh[h][1]);
        a0 += u.x * sc; a1 += u.y * sc;
        a2 += w.x * sc; a3 += w.y * sc;
    }
    float2* A2 = (float2*)(avg_out + (size_t)bt * LS_);
    A2[tid]       = make_float2(a0, a1);
    A2[tid + 512] = make_float2(a2, a3);
}

// ---------------------------------------------------------------------------
// Context (fp16, K=2048): ctx = (E·v) * inv. grid (1, 4, 96).
// ---------------------------------------------------------------------------
__global__ __launch_bounds__(256, 2) void ctx_mma(
    const __half* __restrict__ E,
    const __half* __restrict__ KV1, const __half* __restrict__ KV2,
    const float* __restrict__ Inv,
    __nv_bfloat16* __restrict__ Cs)
{
    extern __shared__ char smx[];
    const uint32_t base = smem_u32(smx);

    const int tid  = threadIdx.x;
    const int warp = tid >> 5, lane = tid & 31;
    const int wm = warp >> 2, wn = warp & 3;
    const int z = blockIdx.z;
    const int b = z / H_, h = z % H_;
    const int m0 = blockIdx.y * 128;

    const int rA = tid >> 3;
    const int c8 = (tid & 7) * 8;
    const __half* aP = E + ((size_t)z * LO_ + m0 + rA) * LS_ + c8;
    const uint32_t off0 = 2u * (rA * PADC + c8);
    const __half* v1b = KV1 + (size_t)b * LV_ * E2_ + E_ + h * D_ + c8;
    const __half* v2b = KV2 + (size_t)b * LL_ * E2_ + E_ + h * D_ + c8;

    #define CLOAD(j) do { \
        int _ko = (j) * 64; \
        uint32_t _sb = base + ((j) % 3) * STGC; \
        _Pragma("unroll") \
        for (int _i = 0; _i < 4; _i++) \
            cpa16(_sb + off0 + _i * (2 * 32 * PADC), aP + _ko + (size_t)_i * 32 * LS_); \
        _Pragma("unroll") \
        for (int _i = 0; _i < 2; _i++) { \
            int _s = _ko + rA + 32 * _i; \
            const __half* _src = (_s < LV_) ? v1b + (size_t)_s * E2_ \
                                            : v2b + (size_t)(_s - LV_) * E2_; \
            cpa16(_sb + TILE64B + off0 + _i * (2 * 32 * PADC), _src); \
        } \
        asm volatile("cp.async.commit_group;" ::: "memory"); \
    } while (0)

    CLOAD(0); CLOAD(1);

    const int lr = lane & 15;
    const int lh = (lane >> 4) * 8;
    const int tg  = lane >> 3;
    const int tlr = lane & 7;
    const int tko = (tg & 1) * 8;
    const int tno = (tg >> 1) * 8;

    float acc[4][2][4];
    #pragma unroll
    for (int i = 0; i < 4; i++)
        #pragma unroll
        for (int j = 0; j < 2; j++)
            #pragma unroll
            for (int q = 0; q < 4; q++) acc[i][j][q] = 0.f;

    const int NCHUNK = 32;
    for (int c = 0; c < NCHUNK; c++) {
        asm volatile("cp.async.wait_group 1;" ::: "memory");
        __syncthreads();
        if (c + 2 < NCHUNK) CLOAD(c + 2);
        else asm volatile("cp.async.commit_group;" ::: "memory");

        const uint32_t ab = base + (c % 3) * STGC;
        const uint32_t bb = ab + TILE64B;
        #pragma unroll
        for (int kf = 0; kf < 4; kf++) {
            uint32_t a[4][4];
            #pragma unroll
            for (int mi = 0; mi < 4; mi++)
                ldm_x4(a[mi][0], a[mi][1], a[mi][2], a[mi][3],
                       ab + 2u * ((wm * 64 + mi * 16 + lr) * PADC + kf * 16 + lh));
            uint32_t rb[4];
            ldm_x4_t(rb[0], rb[1], rb[2], rb[3],
                     bb + 2u * ((kf * 16 + tko + tlr) * PADC + wn * 16 + tno));
            #pragma unroll
            for (int mi = 0; mi < 4; mi++)
                #pragma unroll
                for (int nb = 0; nb < 2; nb++)
                    mma_hf(acc[mi][nb], a[mi], rb[nb * 2], rb[nb * 2 + 1]);
        }
    }
    #undef CLOAD

    const int er = lane >> 2;
    const int ec = (lane & 3) * 2;
    #pragma unroll
    for (int mi = 0; mi < 4; mi++) {
        int m = m0 + wm * 64 + mi * 16 + er;
        float inv0 = __ldg(Inv + (size_t)z * LO_ + m);
        float inv1 = __ldg(Inv + (size_t)z * LO_ + m + 8);
        #pragma unroll
        for (int nb = 0; nb < 2; nb++) {
            int nl = wn * 16 + nb * 8 + ec;
            __nv_bfloat16* d0 = Cs + (size_t)(b * LO_ + m) * RS2 + h * D_ + nl;
            __nv_bfloat16* d1 = Cs + (size_t)(b * LO_ + m + 8) * RS2 + h * D_ + nl;
            __nv_bfloat16 h0, l0, h1, l1;
            fsplit_bf(acc[mi][nb][0] * inv0, h0, l0);
            fsplit_bf(acc[mi][nb][1] * inv0, h1, l1);
            *(__nv_bfloat162*)(d0)      = __nv_bfloat162(h0, h1);
            *(__nv_bfloat162*)(d0 + E_) = __nv_bfloat162(l0, l1);
            fsplit_bf(acc[mi][nb][2] * inv1, h0, l0);
            fsplit_bf(acc[mi][nb][3] * inv1, h1, l1);
            *(__nv_bfloat162*)(d1)      = __nv_bfloat162(h0, h1);
            *(__nv_bfloat162*)(d1 + E_) = __nv_bfloat162(l0, l1);
        }
    }
}

// ---------------------------------------------------------------------------
// Launch
// ---------------------------------------------------------------------------
extern "C" void kernel_launch(void* const* d_in, const int* in_sizes, int n_in,
                              void* d_out, int out_size)
{
    (void)in_sizes; (void)n_in; (void)out_size;

    const float* V    = (const float*)d_in[0];
    const float* L    = (const float*)d_in[1];
    const float* O    = (const float*)d_in[2];
    const float* mask = (const float*)d_in[3];
    const float* w1   = (const float*)d_in[4];
    const float* b1   = (const float*)d_in[5];
    const float* w2   = (const float*)d_in[6];
    const float* b2   = (const float*)d_in[7];
    const float* ow   = (const float*)d_in[8];
    const float* ob   = (const float*)d_in[9];

    float* out = (float*)d_out;
    float* avg = out + (size_t)B_ * LO_ * E_;

    __half *Oh, *Vh, *Lh, *w1h, *w2h, *qq, *kv1, *kv2, *Eh;
    __nv_bfloat16 *ctxsp, *owsp;
    float* Inv;
    cudaGetSymbolAddress((void**)&Oh,    g_Oh);
    cudaGetSymbolAddress((void**)&Vh,    g_Vh);
    cudaGetSymbolAddress((void**)&Lh,    g_Lh);
    cudaGetSymbolAddress((void**)&w1h,   g_w1h);
    cudaGetSymbolAddress((void**)&w2h,   g_w2h);
    cudaGetSymbolAddress((void**)&ctxsp, g_ctxsp);
    cudaGetSymbolAddress((void**)&owsp,  g_owsp);
    cudaGetSymbolAddress((void**)&qq,    g_qq);
    cudaGetSymbolAddress((void**)&kv1,   g_kv1);
    cudaGetSymbolAddress((void**)&kv2,   g_kv2);
    cudaGetSymbolAddress((void**)&Eh,    g_Eh);
    cudaGetSymbolAddress((void**)&Inv,   g_inv);

    cudaFuncSetAttribute(proj_qkv, cudaFuncAttributeMaxDynamicSharedMemorySize, SMEM_PROJ);
    cudaFuncSetAttribute(proj_out, cudaFuncAttributeMaxDynamicSharedMemorySize, SMEM_PROJ);
    cudaFuncSetAttribute(ctx_mma,  cudaFuncAttributeMaxDynamicSharedMemorySize, SMEM_CTX);

    // 1) Fused splits
    split_all<<<(ROW * (E_ / 4)) / 256, 256>>>(V, L, O, w1, w2, ow,
                                               Vh, Lh, Oh, w1h, w2h, owsp);

    // 2) q/k/v projections (fp16 1-plane, K'=768)
    dim3 gP(E2_ / 128, (B_ * LV_) / 128, 3);
    proj_qkv<<<gP, 256, SMEM_PROJ>>>(Oh, Vh, Lh, w1h, w2h, b1, b2, qq, kv1, kv2);

    // 3) Scores -> E = exp(s)
    dim3 gS(LS_ / 128, LO_ / 128, Z_);
    scores_mma<<<gS, 256>>>(qq, kv1, kv2, mask, Eh);

    // 4) Rowsum -> inv + avg
    rowsum_kernel<<<B_ * LO_, 512>>>(Eh, Inv, avg);

    // 5) Context (normalize in epilogue) -> bf16 split ctx
    dim3 gC(1, LO_ / 128, Z_);
    ctx_mma<<<gC, 256, SMEM_CTX>>>(Eh, kv1, kv2, Inv, ctxsp);

    // 6) Output projection (bf16 3-term)
    dim3 gO(E_ / 128, (B_ * LO_) / 128);
    proj_out<<<gO, 256, SMEM_PROJ>>>(ctxsp, owsp, ob, out);
}